// round 8
// baseline (speedup 1.0000x reference)
#include <cuda_runtime.h>
#include <cstdint>
#include <math.h>

#define B_   32
#define N_   4096
#define D_   256
#define S_   8
#define H_   512
#define TOK  (B_*N_)      // 131072
#define EPS  1e-5f
#define SCALE 0.0625f     // 256^-0.5

// ---------------- scratch (device globals) ----------------------------------
__device__ float g_mean[TOK];
__device__ float g_rstd[TOK];
__device__ float g_slots[B_*S_*D_];
__device__ float g_p[B_*S_*D_];      // pg = SCALE * g ∘ (q @ wk)
__device__ float g_S1[B_*S_];
__device__ float g_S2[B_*S_];
__device__ float g_attn[TOK*S_];     // last iter only
__device__ float g_cs[B_*S_];
__device__ float g_t1[B_*S_];
__device__ float g_U[B_*S_*D_];
__device__ float g_wkb[D_];          // wk @ ln_in_b + bk
__device__ float g_MgT[D_*D_];       // MgT[t][d] = SCALE*g[t]*sum_j wq[j][d]*wk[j][t]
__device__ float g_cgt[D_];          // SCALE*g[t]*sum_j bq[j]*wk[j][t]
__device__ float g_wS1[D_];          // sum_t MgT[t][d]
__device__ float g_uS2[D_];          // SCALE*sum_t wq[t][d]*wkb[t]
__device__ float g_gammaS1;          // sum_t cgt[t]
__device__ float g_betaS2;           // SCALE*sum_t bq[t]*wkb[t]

__device__ __forceinline__ float sigmoidf_(float x) { return 1.f / (1.f + expf(-x)); }

// ---------------- prep 1: wkb ------------------------------------------------
__global__ void k_prep_wkb(const float* __restrict__ wk, const float* __restrict__ lnb,
                           const float* __restrict__ bk) {
    int j = threadIdx.x;
    const float* wr = wk + (size_t)j * 256;
    float acc = bk[j];
    #pragma unroll 4
    for (int e = 0; e < 256; e += 4) {
        float4 w4 = *(const float4*)&wr[e];
        float4 b4 = *(const float4*)&lnb[e];
        acc += w4.x*b4.x + w4.y*b4.y + w4.z*b4.z + w4.w*b4.w;
    }
    g_wkb[j] = acc;
}

// ---------------- prep 2: MgT row tcol ---------------------------------------
__global__ void k_prep_M(const float* __restrict__ wq, const float* __restrict__ wk,
                         const float* __restrict__ bq, const float* __restrict__ lng) {
    __shared__ float swk[256];
    __shared__ float sc;
    int tcol = blockIdx.x;
    int d = threadIdx.x;
    swk[d] = wk[(size_t)d*256 + tcol];
    __syncthreads();
    float acc = 0.f;
    #pragma unroll 4
    for (int j = 0; j < 256; j++) acc += wq[(size_t)j*256 + d] * swk[j];
    if (d < 32) {
        float c = 0.f;
        #pragma unroll
        for (int j = d; j < 256; j += 32) c += bq[j]*swk[j];
        #pragma unroll
        for (int o = 16; o; o >>= 1) c += __shfl_xor_sync(0xffffffffu, c, o);
        if (d == 0) sc = c;
    }
    __syncthreads();
    float gt = lng[tcol];
    g_MgT[(size_t)tcol*256 + d] = SCALE * gt * acc;
    if (d == 0) g_cgt[tcol] = SCALE * gt * sc;
}

// ---------------- prep 3: S1/S2 vectors --------------------------------------
__global__ void k_prep_vec(const float* __restrict__ wq, const float* __restrict__ bq) {
    __shared__ float red[8];
    int d = threadIdx.x;
    float a1 = 0.f, a2 = 0.f;
    for (int t = 0; t < 256; t++) {
        a1 += g_MgT[(size_t)t*256 + d];
        a2 += wq[(size_t)t*256 + d] * g_wkb[t];
    }
    g_wS1[d] = a1;
    g_uS2[d] = SCALE * a2;
    // gamma = sum cgt; beta = SCALE * sum bq*wkb
    float p = g_cgt[d];
    float qv = bq[d] * g_wkb[d];
    int w = d >> 5, lane = d & 31;
    #pragma unroll
    for (int o = 16; o; o >>= 1) p += __shfl_xor_sync(0xffffffffu, p, o);
    if (lane == 0) red[w] = p;
    __syncthreads();
    if (d == 0) {
        float s = 0.f;
        #pragma unroll
        for (int i = 0; i < 8; i++) s += red[i];
        g_gammaS1 = s;
    }
    __syncthreads();
    #pragma unroll
    for (int o = 16; o; o >>= 1) qv += __shfl_xor_sync(0xffffffffu, qv, o);
    if (lane == 0) red[w] = qv;
    __syncthreads();
    if (d == 0) {
        float s = 0.f;
        #pragma unroll
        for (int i = 0; i < 8; i++) s += red[i];
        g_betaS2 = SCALE * s;
    }
}

// ---------------- K1: per-token mean/rstd ------------------------------------
__global__ void k_meanvar(const float* __restrict__ x) {
    int warp = threadIdx.x >> 5, lane = threadIdx.x & 31;
    int tok = blockIdx.x * 8 + warp;
    const float4* row = (const float4*)(x + (size_t)tok * D_);
    float4 a = row[lane*2], b = row[lane*2+1];
    float s = a.x+a.y+a.z+a.w + b.x+b.y+b.z+b.w;
    float q = a.x*a.x+a.y*a.y+a.z*a.z+a.w*a.w + b.x*b.x+b.y*b.y+b.z*b.z+b.w*b.w;
    #pragma unroll
    for (int o = 16; o; o >>= 1) {
        s += __shfl_xor_sync(0xffffffffu, s, o);
        q += __shfl_xor_sync(0xffffffffu, q, o);
    }
    if (lane == 0) {
        float m = s * (1.f/256.f);
        g_mean[tok] = m;
        g_rstd[tok] = rsqrtf(q * (1.f/256.f) - m*m + EPS);
    }
}

// ---------------- K4: qproj (single matvec via MgT) --------------------------
__global__ void __launch_bounds__(256) k_qproj4(
    const float* __restrict__ g, const float* __restrict__ bln,
    int init,
    const float* __restrict__ noise, const float* __restrict__ mu,
    const float* __restrict__ sigma_raw)
{
    __shared__ __align__(16) float sa[8][256];
    __shared__ float sm[8], sr[8];
    int b = blockIdx.x, t = threadIdx.x;
    int w = t >> 5, lane = t & 31;

    if (init) {
        float sr_ = sigma_raw[t];
        float sp = (sr_ > 20.f) ? sr_ : log1pf(expf(sr_));
        float muv = mu[t];
        #pragma unroll
        for (int s = 0; s < 8; s++) {
            float v = muv + sp * noise[(b*8+s)*256 + t];
            sa[s][t] = v;
            g_slots[(b*8+s)*256 + t] = v;
            g_U[(b*8+s)*256 + t] = 0.f;
        }
    } else {
        #pragma unroll
        for (int s = 0; s < 8; s++) {
            g_U[(b*8+s)*256 + t] = 0.f;
            sa[s][t] = g_slots[(b*8+s)*256 + t];
        }
    }
    if (t < 8) { g_cs[b*8 + t] = 0.f; g_t1[b*8 + t] = 0.f; }
    __syncthreads();

    // stats: warp w handles slot w
    {
        float s1 = 0.f, s2 = 0.f;
        #pragma unroll
        for (int e = 0; e < 8; e++) {
            float v = sa[w][lane + e*32];
            s1 += v; s2 += v*v;
        }
        #pragma unroll
        for (int o = 16; o; o >>= 1) {
            s1 += __shfl_xor_sync(0xffffffffu, s1, o);
            s2 += __shfl_xor_sync(0xffffffffu, s2, o);
        }
        if (lane == 0) {
            float m = s1 * (1.f/256.f);
            sm[w] = m;
            sr[w] = rsqrtf(s2 * (1.f/256.f) - m*m + EPS);
        }
    }
    __syncthreads();
    float gt = g[t], bt = bln[t];
    #pragma unroll
    for (int s = 0; s < 8; s++)
        sa[s][t] = (sa[s][t] - sm[s]) * sr[s] * gt + bt;
    __syncthreads();

    // pg[s][t] = sa[s] · MgT[t,:] + cgt[t]
    {
        float acc[8] = {0,0,0,0,0,0,0,0};
        const float* wr = g_MgT + (size_t)t * 256;
        #pragma unroll 2
        for (int e = 0; e < 256; e += 4) {
            float4 w4 = *(const float4*)&wr[e];
            #pragma unroll
            for (int s = 0; s < 8; s++) {
                float4 a4 = *(const float4*)&sa[s][e];
                acc[s] += w4.x*a4.x + w4.y*a4.y + w4.z*a4.z + w4.w*a4.w;
            }
        }
        float cg = g_cgt[t];
        #pragma unroll
        for (int s = 0; s < 8; s++)
            g_p[(b*8+s)*256 + t] = acc[s] + cg;
    }

    // S1[s] = sa[s]·wS1 + gamma ; S2[s] = sa[s]·uS2 + beta   (warp w = slot w)
    {
        float d1 = 0.f, d2 = 0.f;
        #pragma unroll
        for (int e = lane; e < 256; e += 32) {
            float av = sa[w][e];
            d1 += av * g_wS1[e];
            d2 += av * g_uS2[e];
        }
        #pragma unroll
        for (int o = 16; o; o >>= 1) {
            d1 += __shfl_xor_sync(0xffffffffu, d1, o);
            d2 += __shfl_xor_sync(0xffffffffu, d2, o);
        }
        if (lane == 0) {
            g_S1[b*8 + w] = d1 + g_gammaS1;
            g_S2[b*8 + w] = d2 + g_betaS2;
        }
    }
}

// ---------------- K5: fused attn (pg in smem, 4 CTAs/SM) ---------------------
__global__ void __launch_bounds__(256, 4) k_attn2(const float* __restrict__ x,
                                                  int store_attn) {
    // spg layout: [lg(4)][s(8)][li(8)][12 floats] — conflict-free LDS.128
    __shared__ float spg[4*768];
    __shared__ __align__(16) float sA[32][8];
    int b = blockIdx.y, chunk = blockIdx.x;
    int t = threadIdx.x;
    int wid = t >> 5, lane = t & 31;
    int slot = (lane >> 2) & 7;

    // fill spg: pg[s][d] -> spg[(d>>3)>>3 ...]: l = d>>3
    {
        const float* pb = g_p + b*S_*D_;
        #pragma unroll
        for (int idx = t; idx < 2048; idx += 256) {
            int s = idx >> 8, d = idx & 255;
            int l = d >> 3, e = d & 7;
            spg[(l >> 3)*768 + s*96 + (l & 7)*12 + e] = pb[s*256 + d];
        }
    }
    __syncthreads();
    int pbase = (lane >> 3)*768 + (lane & 7)*12;

    float S1l = g_S1[b*8 + slot];
    float S2l = g_S2[b*8 + slot];

    float u[8]  = {0,0,0,0,0,0,0,0};
    float csA = 0.f, t1A = 0.f;
    int base_tok = b*N_ + chunk*256;

    for (int sub = 0; sub < 8; sub++) {
        int sub0 = sub * 32;
        #pragma unroll
        for (int i = 0; i < 4; i++) {
            int loc = sub0 + wid*4 + i;
            int n = base_tok + loc;
            const float* xr = x + (size_t)n*256 + lane*8;
            float4 xa = *(const float4*)xr;
            float4 xb = *(const float4*)(xr + 4);
            float dt[8];
            #pragma unroll
            for (int s = 0; s < 8; s++) {
                const float* pp = spg + pbase + s*96;
                float4 A  = *(const float4*)pp;
                float4 Bv = *(const float4*)(pp + 4);
                dt[s] = xa.x*A.x + xa.y*A.y + xa.z*A.z + xa.w*A.w
                      + xb.x*Bv.x + xb.y*Bv.y + xb.z*Bv.z + xb.w*Bv.w;
            }
            // halving-tree reduction (16 shfl)
            float e0, e1, e2, e3;
            {
                float r0 = __shfl_xor_sync(0xffffffffu, dt[0], 16);
                float r1 = __shfl_xor_sync(0xffffffffu, dt[1], 16);
                float r2 = __shfl_xor_sync(0xffffffffu, dt[2], 16);
                float r3 = __shfl_xor_sync(0xffffffffu, dt[3], 16);
                float r4 = __shfl_xor_sync(0xffffffffu, dt[4], 16);
                float r5 = __shfl_xor_sync(0xffffffffu, dt[5], 16);
                float r6 = __shfl_xor_sync(0xffffffffu, dt[6], 16);
                float r7 = __shfl_xor_sync(0xffffffffu, dt[7], 16);
                bool hi = (lane & 16) != 0;
                e0 = hi ? (dt[4]+r4) : (dt[0]+r0);
                e1 = hi ? (dt[5]+r5) : (dt[1]+r1);
                e2 = hi ? (dt[6]+r6) : (dt[2]+r2);
                e3 = hi ? (dt[7]+r7) : (dt[3]+r3);
            }
            float f0, f1;
            {
                float r0 = __shfl_xor_sync(0xffffffffu, e0, 8);
                float r1 = __shfl_xor_sync(0xffffffffu, e1, 8);
                float r2 = __shfl_xor_sync(0xffffffffu, e2, 8);
                float r3 = __shfl_xor_sync(0xffffffffu, e3, 8);
                bool hi = (lane & 8) != 0;
                f0 = hi ? (e2+r2) : (e0+r0);
                f1 = hi ? (e3+r3) : (e1+r1);
            }
            float v;
            {
                float r0 = __shfl_xor_sync(0xffffffffu, f0, 4);
                float r1 = __shfl_xor_sync(0xffffffffu, f1, 4);
                bool hi = (lane & 4) != 0;
                v = hi ? (f1+r1) : (f0+r0);
            }
            v += __shfl_xor_sync(0xffffffffu, v, 2);
            v += __shfl_xor_sync(0xffffffffu, v, 1);

            float r = g_rstd[n], m = g_mean[n];
            float rm = r * m;
            float lg = r*v - rm*S1l + S2l;
            float mx = lg;
            mx = fmaxf(mx, __shfl_xor_sync(0xffffffffu, mx, 4));
            mx = fmaxf(mx, __shfl_xor_sync(0xffffffffu, mx, 8));
            mx = fmaxf(mx, __shfl_xor_sync(0xffffffffu, mx, 16));
            float e = expf(lg - mx);
            float sum = e;
            sum += __shfl_xor_sync(0xffffffffu, sum, 4);
            sum += __shfl_xor_sync(0xffffffffu, sum, 8);
            sum += __shfl_xor_sync(0xffffffffu, sum, 16);
            float a = e / sum + 1e-8f;
            float ar = a * r;
            csA += a;
            t1A += a * rm;
            if ((lane & 3) == 0) {
                sA[loc - sub0][slot] = ar;
                if (store_attn) g_attn[(size_t)n*8 + slot] = a;
            }
        }
        __syncthreads();
        const float* xcol = x + (size_t)(base_tok + sub0)*256 + t;
        #pragma unroll 8
        for (int i = 0; i < 32; i++) {
            float xv = xcol[(size_t)i*256];
            float4 p0 = *(const float4*)&sA[i][0];
            float4 p1 = *(const float4*)&sA[i][4];
            u[0] += p0.x*xv; u[1] += p0.y*xv; u[2] += p0.z*xv; u[3] += p0.w*xv;
            u[4] += p1.x*xv; u[5] += p1.y*xv; u[6] += p1.z*xv; u[7] += p1.w*xv;
        }
        __syncthreads();
    }

    #pragma unroll
    for (int s = 0; s < 8; s++)
        atomicAdd(&g_U[(b*8+s)*256 + t], u[s]);
    if ((lane & 3) == 0) {
        atomicAdd(&g_cs[b*8 + slot], csA);
        atomicAdd(&g_t1[b*8 + slot], t1A);
    }
}

// ---------------- K7: GRU + LN + MLP, 4 slots per CTA ------------------------
__global__ void __launch_bounds__(256) k_gru4(
    const float* __restrict__ lng_in, const float* __restrict__ lnb_in,
    const float* __restrict__ wv,   const float* __restrict__ bv,
    const float* __restrict__ w_ih, const float* __restrict__ w_hh,
    const float* __restrict__ b_ih, const float* __restrict__ b_hh,
    const float* __restrict__ lng,  const float* __restrict__ lnb,
    const float* __restrict__ w1,   const float* __restrict__ b1,
    const float* __restrict__ w2,   const float* __restrict__ b2,
    float* __restrict__ out_slots)
{
    __shared__ __align__(16) float szn[4][256];
    __shared__ __align__(16) float su[4][256];
    __shared__ __align__(16) float sh[4][256];
    __shared__ __align__(16) float sa[4][256];
    __shared__ __align__(16) float sh1[4][512];
    __shared__ float sm[4], sr2[4];

    int b = blockIdx.x >> 1;
    int grp = blockIdx.x & 1;
    int row0 = b*8 + grp*4;
    int t = threadIdx.x;

    #pragma unroll
    for (int sl = 0; sl < 4; sl++) {
        int row = row0 + sl;
        float csv = g_cs[row], t1v = g_t1[row];
        float Ut = g_U[row*256 + t];
        szn[sl][t] = lng_in[t] * (Ut - t1v) / csv + lnb_in[t];
        sh[sl][t] = g_slots[row*256 + t];
    }
    __syncthreads();

    {
        float a[4] = {0,0,0,0};
        const float* wr = wv + (size_t)t * 256;
        #pragma unroll 2
        for (int e = 0; e < 256; e += 4) {
            float4 w4 = *(const float4*)&wr[e];
            #pragma unroll
            for (int sl = 0; sl < 4; sl++) {
                float4 z = *(const float4*)&szn[sl][e];
                a[sl] += w4.x*z.x + w4.y*z.y + w4.z*z.z + w4.w*z.w;
            }
        }
        float bvt = bv[t];
        #pragma unroll
        for (int sl = 0; sl < 4; sl++) su[sl][t] = a[sl] + bvt;
    }
    __syncthreads();

    float xr[4], xz[4], xn[4], hr[4], hz[4], hn[4];
    #pragma unroll
    for (int sl = 0; sl < 4; sl++) {
        xr[sl] = b_ih[t]; xz[sl] = b_ih[256+t]; xn[sl] = b_ih[512+t];
        hr[sl] = b_hh[t]; hz[sl] = b_hh[256+t]; hn[sl] = b_hh[512+t];
    }
    const float* wir = w_ih + (size_t)t*256;
    const float* wiz = w_ih + (size_t)(256+t)*256;
    const float* win = w_ih + (size_t)(512+t)*256;
    const float* whr = w_hh + (size_t)t*256;
    const float* whz = w_hh + (size_t)(256+t)*256;
    const float* whn = w_hh + (size_t)(512+t)*256;

    for (int e = 0; e < 256; e += 4) {
        float4 wr4 = *(const float4*)&wir[e];
        float4 wz4 = *(const float4*)&wiz[e];
        float4 wn4 = *(const float4*)&win[e];
        float4 vr4 = *(const float4*)&whr[e];
        float4 vz4 = *(const float4*)&whz[e];
        float4 vn4 = *(const float4*)&whn[e];
        #pragma unroll
        for (int sl = 0; sl < 4; sl++) {
            float4 u4 = *(const float4*)&su[sl][e];
            float4 h4 = *(const float4*)&sh[sl][e];
            xr[sl] += wr4.x*u4.x + wr4.y*u4.y + wr4.z*u4.z + wr4.w*u4.w;
            xz[sl] += wz4.x*u4.x + wz4.y*u4.y + wz4.z*u4.z + wz4.w*u4.w;
            xn[sl] += wn4.x*u4.x + wn4.y*u4.y + wn4.z*u4.z + wn4.w*u4.w;
            hr[sl] += vr4.x*h4.x + vr4.y*h4.y + vr4.z*h4.z + vr4.w*h4.w;
            hz[sl] += vz4.x*h4.x + vz4.y*h4.y + vz4.z*h4.z + vz4.w*h4.w;
            hn[sl] += vn4.x*h4.x + vn4.y*h4.y + vn4.z*h4.z + vn4.w*h4.w;
        }
    }
    float hnew[4];
    #pragma unroll
    for (int sl = 0; sl < 4; sl++) {
        float r = sigmoidf_(xr[sl] + hr[sl]);
        float z = sigmoidf_(xz[sl] + hz[sl]);
        float nn = tanhf(xn[sl] + r*hn[sl]);
        hnew[sl] = (1.f - z)*nn + z*sh[sl][t];
    }
    __syncthreads();
    #pragma unroll
    for (int sl = 0; sl < 4; sl++) su[sl][t] = hnew[sl];
    __syncthreads();
    int w = t >> 5, lane = t & 31;
    if (w < 4) {
        float s1 = 0.f, s2 = 0.f;
        #pragma unroll
        for (int e = 0; e < 8; e++) {
            float v = su[w][lane + e*32];
            s1 += v; s2 += v*v;
        }
        #pragma unroll
        for (int o = 16; o; o >>= 1) {
            s1 += __shfl_xor_sync(0xffffffffu, s1, o);
            s2 += __shfl_xor_sync(0xffffffffu, s2, o);
        }
        if (lane == 0) {
            float m = s1 * (1.f/256.f);
            sm[w] = m;
            sr2[w] = rsqrtf(s2 * (1.f/256.f) - m*m + EPS);
        }
    }
    __syncthreads();
    float gt = lng[t], bt = lnb[t];
    #pragma unroll
    for (int sl = 0; sl < 4; sl++)
        sa[sl][t] = (hnew[sl] - sm[sl]) * sr2[sl] * gt + bt;
    __syncthreads();

    float a1[4] = {b1[t], b1[t], b1[t], b1[t]};
    float a2[4] = {b1[256+t], b1[256+t], b1[256+t], b1[256+t]};
    const float* w1a = w1 + (size_t)t*256;
    const float* w1b = w1 + (size_t)(256+t)*256;
    for (int e = 0; e < 256; e += 4) {
        float4 wa = *(const float4*)&w1a[e];
        float4 wb = *(const float4*)&w1b[e];
        #pragma unroll
        for (int sl = 0; sl < 4; sl++) {
            float4 s4 = *(const float4*)&sa[sl][e];
            a1[sl] += wa.x*s4.x + wa.y*s4.y + wa.z*s4.z + wa.w*s4.w;
            a2[sl] += wb.x*s4.x + wb.y*s4.y + wb.z*s4.z + wb.w*s4.w;
        }
    }
    #pragma unroll
    for (int sl = 0; sl < 4; sl++) {
        sh1[sl][t]     = fmaxf(a1[sl], 0.f);
        sh1[sl][256+t] = fmaxf(a2[sl], 0.f);
    }
    __syncthreads();

    float o[4] = {b2[t], b2[t], b2[t], b2[t]};
    const float* w2r = w2 + (size_t)t*512;
    for (int e = 0; e < 512; e += 4) {
        float4 w4 = *(const float4*)&w2r[e];
        #pragma unroll
        for (int sl = 0; sl < 4; sl++) {
            float4 h4 = *(const float4*)&sh1[sl][e];
            o[sl] += w4.x*h4.x + w4.y*h4.y + w4.z*h4.z + w4.w*h4.w;
        }
    }
    #pragma unroll
    for (int sl = 0; sl < 4; sl++) {
        float res = hnew[sl] + o[sl];
        g_slots[(row0+sl)*256 + t] = res;
        if (out_slots) out_slots[(row0+sl)*256 + t] = res;
    }
}

// ---------------- K8: final attn normalize to d_out --------------------------
__global__ void k_attn_out(float* __restrict__ dst) {
    int i = blockIdx.x*blockDim.x + threadIdx.x;
    if (i < TOK*S_) {
        int s = i & 7;
        int b = i >> 15;
        dst[i] = g_attn[i] / g_cs[b*8 + s];
    }
}

// ---------------- host --------------------------------------------------------
extern "C" void kernel_launch(void* const* d_in, const int* in_sizes, int n_in,
                              void* d_out, int out_size) {
    const float* inputs     = (const float*)d_in[0];
    const float* init_noise = (const float*)d_in[1];
    const float* mu         = (const float*)d_in[2];
    const float* sigma_raw  = (const float*)d_in[3];
    const float* ln_in_g    = (const float*)d_in[4];
    const float* ln_in_b    = (const float*)d_in[5];
    const float* ln_s_g     = (const float*)d_in[6];
    const float* ln_s_b     = (const float*)d_in[7];
    const float* ln_m_g     = (const float*)d_in[8];
    const float* ln_m_b     = (const float*)d_in[9];
    const float* wq         = (const float*)d_in[10];
    const float* bq         = (const float*)d_in[11];
    const float* wk         = (const float*)d_in[12];
    const float* bk         = (const float*)d_in[13];
    const float* wv         = (const float*)d_in[14];
    const float* bv         = (const float*)d_in[15];
    const float* w_ih       = (const float*)d_in[16];
    const float* w_hh       = (const float*)d_in[17];
    const float* b_ih       = (const float*)d_in[18];
    const float* b_hh       = (const float*)d_in[19];
    const float* w1         = (const float*)d_in[20];
    const float* b1         = (const float*)d_in[21];
    const float* w2         = (const float*)d_in[22];
    const float* b2         = (const float*)d_in[23];
    float* out = (float*)d_out;

    k_prep_wkb<<<1, 256>>>(wk, ln_in_b, bk);
    k_prep_M<<<256, 256>>>(wq, wk, bq, ln_in_g);
    k_prep_vec<<<1, 256>>>(wq, bq);
    k_meanvar<<<TOK/8, 256>>>(inputs);

    for (int it = 0; it < 3; ++it) {
        bool last = (it == 2);
        k_qproj4<<<B_, 256>>>(ln_s_g, ln_s_b, it == 0 ? 1 : 0,
                              init_noise, mu, sigma_raw);
        k_attn2<<<dim3(16, B_), 256>>>(inputs, last ? 1 : 0);
        k_gru4<<<B_*2, 256>>>(ln_in_g, ln_in_b, wv, bv,
                              w_ih, w_hh, b_ih, b_hh, ln_m_g, ln_m_b,
                              w1, b1, w2, b2, last ? out : nullptr);
        if (last) k_attn_out<<<(TOK*S_ + 255)/256, 256>>>(out + B_*S_*D_);
    }
}

// round 9
// speedup vs baseline: 1.1298x; 1.1298x over previous
#include <cuda_runtime.h>
#include <cstdint>
#include <math.h>

#define B_   32
#define N_   4096
#define D_   256
#define S_   8
#define H_   512
#define TOK  (B_*N_)      // 131072
#define EPS  1e-5f
#define SCALE 0.0625f     // 256^-0.5

// ---------------- scratch (device globals) ----------------------------------
__device__ float g_mean[TOK];
__device__ float g_rstd[TOK];
__device__ float g_slots[B_*S_*D_];
__device__ float g_p[B_*S_*D_];      // pg = SCALE * g ∘ (q @ wk)
__device__ float g_S1[B_*S_];
__device__ float g_S2[B_*S_];
__device__ float g_attn[TOK*S_];     // last iter only
__device__ float g_cs[B_*S_];
__device__ float g_t1[B_*S_];
__device__ float g_U[B_*S_*D_];
__device__ float g_wkb[D_];          // wk @ ln_in_b + bk
__device__ float g_MgT[D_*D_];       // MgT[t][d] = SCALE*g[t]*sum_j wq[j][d]*wk[j][t]
__device__ float g_cgt[D_];          // SCALE*g[t]*sum_j bq[j]*wk[j][t]
__device__ float g_wS1[D_];          // sum_t MgT[t][d]
__device__ float g_uS2[D_];          // SCALE*sum_t wq[t][d]*wkb[t]
__device__ float g_gammaS1;
__device__ float g_betaS2;

__device__ __forceinline__ float sigmoidf_(float x) { return 1.f / (1.f + expf(-x)); }

// ---------------- prep 1: wkb ------------------------------------------------
__global__ void k_prep_wkb(const float* __restrict__ wk, const float* __restrict__ lnb,
                           const float* __restrict__ bk) {
    int j = threadIdx.x;
    const float* wr = wk + (size_t)j * 256;
    float acc = bk[j];
    #pragma unroll 4
    for (int e = 0; e < 256; e += 4) {
        float4 w4 = *(const float4*)&wr[e];
        float4 b4 = *(const float4*)&lnb[e];
        acc += w4.x*b4.x + w4.y*b4.y + w4.z*b4.z + w4.w*b4.w;
    }
    g_wkb[j] = acc;
}

// ---------------- prep 2: MgT row tcol ---------------------------------------
__global__ void k_prep_M(const float* __restrict__ wq, const float* __restrict__ wk,
                         const float* __restrict__ bq, const float* __restrict__ lng) {
    __shared__ float swk[256];
    __shared__ float sc;
    int tcol = blockIdx.x;
    int d = threadIdx.x;
    swk[d] = wk[(size_t)d*256 + tcol];
    __syncthreads();
    float acc = 0.f;
    #pragma unroll 4
    for (int j = 0; j < 256; j++) acc += wq[(size_t)j*256 + d] * swk[j];
    if (d < 32) {
        float c = 0.f;
        #pragma unroll
        for (int j = d; j < 256; j += 32) c += bq[j]*swk[j];
        #pragma unroll
        for (int o = 16; o; o >>= 1) c += __shfl_xor_sync(0xffffffffu, c, o);
        if (d == 0) sc = c;
    }
    __syncthreads();
    float gt = lng[tcol];
    g_MgT[(size_t)tcol*256 + d] = SCALE * gt * acc;
    if (d == 0) g_cgt[tcol] = SCALE * gt * sc;
}

// ---------------- prep 3: S1/S2 vectors --------------------------------------
__global__ void k_prep_vec(const float* __restrict__ wq, const float* __restrict__ bq) {
    __shared__ float red[8];
    int d = threadIdx.x;
    float a1 = 0.f, a2 = 0.f;
    for (int t = 0; t < 256; t++) {
        a1 += g_MgT[(size_t)t*256 + d];
        a2 += wq[(size_t)t*256 + d] * g_wkb[t];
    }
    g_wS1[d] = a1;
    g_uS2[d] = SCALE * a2;
    float p = g_cgt[d];
    float qv = bq[d] * g_wkb[d];
    int w = d >> 5, lane = d & 31;
    #pragma unroll
    for (int o = 16; o; o >>= 1) p += __shfl_xor_sync(0xffffffffu, p, o);
    if (lane == 0) red[w] = p;
    __syncthreads();
    if (d == 0) {
        float s = 0.f;
        #pragma unroll
        for (int i = 0; i < 8; i++) s += red[i];
        g_gammaS1 = s;
    }
    __syncthreads();
    #pragma unroll
    for (int o = 16; o; o >>= 1) qv += __shfl_xor_sync(0xffffffffu, qv, o);
    if (lane == 0) red[w] = qv;
    __syncthreads();
    if (d == 0) {
        float s = 0.f;
        #pragma unroll
        for (int i = 0; i < 8; i++) s += red[i];
        g_betaS2 = SCALE * s;
    }
}

// ---------------- K1: per-token mean/rstd ------------------------------------
__global__ void k_meanvar(const float* __restrict__ x) {
    int warp = threadIdx.x >> 5, lane = threadIdx.x & 31;
    int tok = blockIdx.x * 8 + warp;
    const float4* row = (const float4*)(x + (size_t)tok * D_);
    float4 a = row[lane*2], b = row[lane*2+1];
    float s = a.x+a.y+a.z+a.w + b.x+b.y+b.z+b.w;
    float q = a.x*a.x+a.y*a.y+a.z*a.z+a.w*a.w + b.x*b.x+b.y*b.y+b.z*b.z+b.w*b.w;
    #pragma unroll
    for (int o = 16; o; o >>= 1) {
        s += __shfl_xor_sync(0xffffffffu, s, o);
        q += __shfl_xor_sync(0xffffffffu, q, o);
    }
    if (lane == 0) {
        float m = s * (1.f/256.f);
        g_mean[tok] = m;
        g_rstd[tok] = rsqrtf(q * (1.f/256.f) - m*m + EPS);
    }
}

// ---------------- K4: qproj (single matvec via MgT) --------------------------
__global__ void __launch_bounds__(256) k_qproj4(
    const float* __restrict__ g, const float* __restrict__ bln,
    int init,
    const float* __restrict__ noise, const float* __restrict__ mu,
    const float* __restrict__ sigma_raw)
{
    __shared__ __align__(16) float sa[8][256];
    __shared__ float sm[8], sr[8];
    int b = blockIdx.x, t = threadIdx.x;
    int w = t >> 5, lane = t & 31;

    if (init) {
        float sr_ = sigma_raw[t];
        float sp = (sr_ > 20.f) ? sr_ : log1pf(expf(sr_));
        float muv = mu[t];
        #pragma unroll
        for (int s = 0; s < 8; s++) {
            float v = muv + sp * noise[(b*8+s)*256 + t];
            sa[s][t] = v;
            g_slots[(b*8+s)*256 + t] = v;
            g_U[(b*8+s)*256 + t] = 0.f;
        }
    } else {
        #pragma unroll
        for (int s = 0; s < 8; s++) {
            g_U[(b*8+s)*256 + t] = 0.f;
            sa[s][t] = g_slots[(b*8+s)*256 + t];
        }
    }
    if (t < 8) { g_cs[b*8 + t] = 0.f; g_t1[b*8 + t] = 0.f; }
    __syncthreads();

    {
        float s1 = 0.f, s2 = 0.f;
        #pragma unroll
        for (int e = 0; e < 8; e++) {
            float v = sa[w][lane + e*32];
            s1 += v; s2 += v*v;
        }
        #pragma unroll
        for (int o = 16; o; o >>= 1) {
            s1 += __shfl_xor_sync(0xffffffffu, s1, o);
            s2 += __shfl_xor_sync(0xffffffffu, s2, o);
        }
        if (lane == 0) {
            float m = s1 * (1.f/256.f);
            sm[w] = m;
            sr[w] = rsqrtf(s2 * (1.f/256.f) - m*m + EPS);
        }
    }
    __syncthreads();
    float gt = g[t], bt = bln[t];
    #pragma unroll
    for (int s = 0; s < 8; s++)
        sa[s][t] = (sa[s][t] - sm[s]) * sr[s] * gt + bt;
    __syncthreads();

    {
        float acc[8] = {0,0,0,0,0,0,0,0};
        const float* wr = g_MgT + (size_t)t * 256;
        #pragma unroll 2
        for (int e = 0; e < 256; e += 4) {
            float4 w4 = *(const float4*)&wr[e];
            #pragma unroll
            for (int s = 0; s < 8; s++) {
                float4 a4 = *(const float4*)&sa[s][e];
                acc[s] += w4.x*a4.x + w4.y*a4.y + w4.z*a4.z + w4.w*a4.w;
            }
        }
        float cg = g_cgt[t];
        #pragma unroll
        for (int s = 0; s < 8; s++)
            g_p[(b*8+s)*256 + t] = acc[s] + cg;
    }

    {
        float d1 = 0.f, d2 = 0.f;
        #pragma unroll
        for (int e = lane; e < 256; e += 32) {
            float av = sa[w][e];
            d1 += av * g_wS1[e];
            d2 += av * g_uS2[e];
        }
        #pragma unroll
        for (int o = 16; o; o >>= 1) {
            d1 += __shfl_xor_sync(0xffffffffu, d1, o);
            d2 += __shfl_xor_sync(0xffffffffu, d2, o);
        }
        if (lane == 0) {
            g_S1[b*8 + w] = d1 + g_gammaS1;
            g_S2[b*8 + w] = d2 + g_betaS2;
        }
    }
}

// ---------------- K5: fused attn (register pg + smem x staging) -------------
__global__ void __launch_bounds__(256, 2) k_attn3(const float* __restrict__ x,
                                                  int store_attn) {
    __shared__ __align__(16) float sX[32][256];   // 32KB x tile
    __shared__ __align__(16) float sA[32][8];
    int b = blockIdx.y, chunk = blockIdx.x;
    int t = threadIdx.x;
    int wid = t >> 5, lane = t & 31;
    int slot = (lane >> 2) & 7;

    float pg[8][8];
    {
        const float* pb = g_p + b*S_*D_;
        #pragma unroll
        for (int s = 0; s < 8; s++) {
            float4 a = *(const float4*)&pb[s*256 + lane*8];
            float4 c = *(const float4*)&pb[s*256 + lane*8 + 4];
            pg[s][0]=a.x; pg[s][1]=a.y; pg[s][2]=a.z; pg[s][3]=a.w;
            pg[s][4]=c.x; pg[s][5]=c.y; pg[s][6]=c.z; pg[s][7]=c.w;
        }
    }
    float S1l = g_S1[b*8 + slot];
    float S2l = g_S2[b*8 + slot];

    float u[8]  = {0,0,0,0,0,0,0,0};
    float csA = 0.f, t1A = 0.f;
    int base_tok = b*N_ + chunk*256;

    for (int sub = 0; sub < 8; sub++) {
        int sub0 = sub * 32;
        #pragma unroll
        for (int i = 0; i < 4; i++) {
            int loc = sub0 + wid*4 + i;
            int li = loc - sub0;
            int n = base_tok + loc;
            const float* xr = x + (size_t)n*256 + lane*8;
            float4 xa = *(const float4*)xr;
            float4 xb = *(const float4*)(xr + 4);
            // stage into smem for pass 2 (single gmem read of x)
            *(float4*)&sX[li][lane*8]     = xa;
            *(float4*)&sX[li][lane*8 + 4] = xb;
            float dt[8];
            #pragma unroll
            for (int s = 0; s < 8; s++) {
                dt[s] = xa.x*pg[s][0] + xa.y*pg[s][1] + xa.z*pg[s][2] + xa.w*pg[s][3]
                      + xb.x*pg[s][4] + xb.y*pg[s][5] + xb.z*pg[s][6] + xb.w*pg[s][7];
            }
            // halving-tree reduction (16 shfl)
            float e0, e1, e2, e3;
            {
                float r0 = __shfl_xor_sync(0xffffffffu, dt[0], 16);
                float r1 = __shfl_xor_sync(0xffffffffu, dt[1], 16);
                float r2 = __shfl_xor_sync(0xffffffffu, dt[2], 16);
                float r3 = __shfl_xor_sync(0xffffffffu, dt[3], 16);
                float r4 = __shfl_xor_sync(0xffffffffu, dt[4], 16);
                float r5 = __shfl_xor_sync(0xffffffffu, dt[5], 16);
                float r6 = __shfl_xor_sync(0xffffffffu, dt[6], 16);
                float r7 = __shfl_xor_sync(0xffffffffu, dt[7], 16);
                bool hi = (lane & 16) != 0;
                e0 = hi ? (dt[4]+r4) : (dt[0]+r0);
                e1 = hi ? (dt[5]+r5) : (dt[1]+r1);
                e2 = hi ? (dt[6]+r6) : (dt[2]+r2);
                e3 = hi ? (dt[7]+r7) : (dt[3]+r3);
            }
            float f0, f1;
            {
                float r0 = __shfl_xor_sync(0xffffffffu, e0, 8);
                float r1 = __shfl_xor_sync(0xffffffffu, e1, 8);
                float r2 = __shfl_xor_sync(0xffffffffu, e2, 8);
                float r3 = __shfl_xor_sync(0xffffffffu, e3, 8);
                bool hi = (lane & 8) != 0;
                f0 = hi ? (e2+r2) : (e0+r0);
                f1 = hi ? (e3+r3) : (e1+r1);
            }
            float v;
            {
                float r0 = __shfl_xor_sync(0xffffffffu, f0, 4);
                float r1 = __shfl_xor_sync(0xffffffffu, f1, 4);
                bool hi = (lane & 4) != 0;
                v = hi ? (f1+r1) : (f0+r0);
            }
            v += __shfl_xor_sync(0xffffffffu, v, 2);
            v += __shfl_xor_sync(0xffffffffu, v, 1);

            float r = g_rstd[n], m = g_mean[n];
            float rm = r * m;
            float lg = r*v - rm*S1l + S2l;
            float mx = lg;
            mx = fmaxf(mx, __shfl_xor_sync(0xffffffffu, mx, 4));
            mx = fmaxf(mx, __shfl_xor_sync(0xffffffffu, mx, 8));
            mx = fmaxf(mx, __shfl_xor_sync(0xffffffffu, mx, 16));
            float e = expf(lg - mx);
            float sum = e;
            sum += __shfl_xor_sync(0xffffffffu, sum, 4);
            sum += __shfl_xor_sync(0xffffffffu, sum, 8);
            sum += __shfl_xor_sync(0xffffffffu, sum, 16);
            float a = e / sum + 1e-8f;
            float ar = a * r;
            csA += a;
            t1A += a * rm;
            if ((lane & 3) == 0) {
                sA[li][slot] = ar;
                if (store_attn) g_attn[(size_t)n*8 + slot] = a;
            }
        }
        __syncthreads();
        // pass 2: U accumulation from smem-staged x
        #pragma unroll 8
        for (int i = 0; i < 32; i++) {
            float xv = sX[i][t];
            float4 p0 = *(const float4*)&sA[i][0];
            float4 p1 = *(const float4*)&sA[i][4];
            u[0] += p0.x*xv; u[1] += p0.y*xv; u[2] += p0.z*xv; u[3] += p0.w*xv;
            u[4] += p1.x*xv; u[5] += p1.y*xv; u[6] += p1.z*xv; u[7] += p1.w*xv;
        }
        __syncthreads();
    }

    #pragma unroll
    for (int s = 0; s < 8; s++)
        atomicAdd(&g_U[(b*8+s)*256 + t], u[s]);
    if ((lane & 3) == 0) {
        atomicAdd(&g_cs[b*8 + slot], csA);
        atomicAdd(&g_t1[b*8 + slot], t1A);
    }
}

// ---------------- K7: GRU + LN + MLP, block per (batch, slot-pair) ----------
__global__ void __launch_bounds__(256) k_gru3(
    const float* __restrict__ lng_in, const float* __restrict__ lnb_in,
    const float* __restrict__ wv,   const float* __restrict__ bv,
    const float* __restrict__ w_ih, const float* __restrict__ w_hh,
    const float* __restrict__ b_ih, const float* __restrict__ b_hh,
    const float* __restrict__ lng,  const float* __restrict__ lnb,
    const float* __restrict__ w1,   const float* __restrict__ b1,
    const float* __restrict__ w2,   const float* __restrict__ b2,
    float* __restrict__ out_slots)
{
    __shared__ __align__(16) float szn[2][256];
    __shared__ __align__(16) float su[2][256];
    __shared__ __align__(16) float sh[2][256];
    __shared__ __align__(16) float sa[2][256];
    __shared__ __align__(16) float sh1[2][512];
    __shared__ float sm[2], sr2[2];

    int b = blockIdx.x >> 2;
    int p = blockIdx.x & 3;
    int row0 = b*8 + p*2;
    int t = threadIdx.x;

    #pragma unroll
    for (int sl = 0; sl < 2; sl++) {
        int row = row0 + sl;
        float csv = g_cs[row], t1v = g_t1[row];
        float Ut = g_U[row*256 + t];
        szn[sl][t] = lng_in[t] * (Ut - t1v) / csv + lnb_in[t];
        sh[sl][t] = g_slots[row*256 + t];
    }
    __syncthreads();

    {
        float a0 = 0.f, a1 = 0.f;
        const float* wr = wv + (size_t)t * 256;
        #pragma unroll 2
        for (int e = 0; e < 256; e += 4) {
            float4 w4 = *(const float4*)&wr[e];
            float4 z0 = *(const float4*)&szn[0][e];
            float4 z1 = *(const float4*)&szn[1][e];
            a0 += w4.x*z0.x + w4.y*z0.y + w4.z*z0.z + w4.w*z0.w;
            a1 += w4.x*z1.x + w4.y*z1.y + w4.z*z1.z + w4.w*z1.w;
        }
        float bvt = bv[t];
        su[0][t] = a0 + bvt;
        su[1][t] = a1 + bvt;
    }
    __syncthreads();

    float xr[2], xz[2], xn[2], hr[2], hz[2], hn[2];
    #pragma unroll
    for (int sl = 0; sl < 2; sl++) {
        xr[sl] = b_ih[t]; xz[sl] = b_ih[256+t]; xn[sl] = b_ih[512+t];
        hr[sl] = b_hh[t]; hz[sl] = b_hh[256+t]; hn[sl] = b_hh[512+t];
    }
    const float* wir = w_ih + (size_t)t*256;
    const float* wiz = w_ih + (size_t)(256+t)*256;
    const float* win = w_ih + (size_t)(512+t)*256;
    const float* whr = w_hh + (size_t)t*256;
    const float* whz = w_hh + (size_t)(256+t)*256;
    const float* whn = w_hh + (size_t)(512+t)*256;

    #pragma unroll 2
    for (int e = 0; e < 256; e += 4) {
        float4 wr4 = *(const float4*)&wir[e];
        float4 wz4 = *(const float4*)&wiz[e];
        float4 wn4 = *(const float4*)&win[e];
        float4 vr4 = *(const float4*)&whr[e];
        float4 vz4 = *(const float4*)&whz[e];
        float4 vn4 = *(const float4*)&whn[e];
        #pragma unroll
        for (int sl = 0; sl < 2; sl++) {
            float4 u4 = *(const float4*)&su[sl][e];
            float4 h4 = *(const float4*)&sh[sl][e];
            xr[sl] += wr4.x*u4.x + wr4.y*u4.y + wr4.z*u4.z + wr4.w*u4.w;
            xz[sl] += wz4.x*u4.x + wz4.y*u4.y + wz4.z*u4.z + wz4.w*u4.w;
            xn[sl] += wn4.x*u4.x + wn4.y*u4.y + wn4.z*u4.z + wn4.w*u4.w;
            hr[sl] += vr4.x*h4.x + vr4.y*h4.y + vr4.z*h4.z + vr4.w*h4.w;
            hz[sl] += vz4.x*h4.x + vz4.y*h4.y + vz4.z*h4.z + vz4.w*h4.w;
            hn[sl] += vn4.x*h4.x + vn4.y*h4.y + vn4.z*h4.z + vn4.w*h4.w;
        }
    }
    float hnew[2];
    #pragma unroll
    for (int sl = 0; sl < 2; sl++) {
        float r = sigmoidf_(xr[sl] + hr[sl]);
        float z = sigmoidf_(xz[sl] + hz[sl]);
        float nn = tanhf(xn[sl] + r*hn[sl]);
        hnew[sl] = (1.f - z)*nn + z*sh[sl][t];
    }
    __syncthreads();
    su[0][t] = hnew[0]; su[1][t] = hnew[1];
    __syncthreads();
    int w = t >> 5, lane = t & 31;
    if (w < 2) {
        float s1 = 0.f, s2 = 0.f;
        #pragma unroll
        for (int e = 0; e < 8; e++) {
            float v = su[w][lane + e*32];
            s1 += v; s2 += v*v;
        }
        #pragma unroll
        for (int o = 16; o; o >>= 1) {
            s1 += __shfl_xor_sync(0xffffffffu, s1, o);
            s2 += __shfl_xor_sync(0xffffffffu, s2, o);
        }
        if (lane == 0) {
            float m = s1 * (1.f/256.f);
            sm[w] = m;
            sr2[w] = rsqrtf(s2 * (1.f/256.f) - m*m + EPS);
        }
    }
    __syncthreads();
    float gt = lng[t], bt = lnb[t];
    sa[0][t] = (hnew[0] - sm[0]) * sr2[0] * gt + bt;
    sa[1][t] = (hnew[1] - sm[1]) * sr2[1] * gt + bt;
    __syncthreads();

    float a1[2] = {b1[t], b1[t]};
    float a2[2] = {b1[256+t], b1[256+t]};
    const float* w1a = w1 + (size_t)t*256;
    const float* w1b = w1 + (size_t)(256+t)*256;
    #pragma unroll 2
    for (int e = 0; e < 256; e += 4) {
        float4 wa = *(const float4*)&w1a[e];
        float4 wb = *(const float4*)&w1b[e];
        #pragma unroll
        for (int sl = 0; sl < 2; sl++) {
            float4 s4 = *(const float4*)&sa[sl][e];
            a1[sl] += wa.x*s4.x + wa.y*s4.y + wa.z*s4.z + wa.w*s4.w;
            a2[sl] += wb.x*s4.x + wb.y*s4.y + wb.z*s4.z + wb.w*s4.w;
        }
    }
    sh1[0][t] = fmaxf(a1[0], 0.f); sh1[0][256+t] = fmaxf(a2[0], 0.f);
    sh1[1][t] = fmaxf(a1[1], 0.f); sh1[1][256+t] = fmaxf(a2[1], 0.f);
    __syncthreads();

    float o[2] = {b2[t], b2[t]};
    const float* w2r = w2 + (size_t)t*512;
    #pragma unroll 2
    for (int e = 0; e < 512; e += 4) {
        float4 w4 = *(const float4*)&w2r[e];
        #pragma unroll
        for (int sl = 0; sl < 2; sl++) {
            float4 h4 = *(const float4*)&sh1[sl][e];
            o[sl] += w4.x*h4.x + w4.y*h4.y + w4.z*h4.z + w4.w*h4.w;
        }
    }
    #pragma unroll
    for (int sl = 0; sl < 2; sl++) {
        float res = hnew[sl] + o[sl];
        g_slots[(row0+sl)*256 + t] = res;
        if (out_slots) out_slots[(row0+sl)*256 + t] = res;
    }
}

// ---------------- K8: final attn normalize to d_out --------------------------
__global__ void k_attn_out(float* __restrict__ dst) {
    int i = blockIdx.x*blockDim.x + threadIdx.x;
    if (i < TOK*S_) {
        int s = i & 7;
        int b = i >> 15;
        dst[i] = g_attn[i] / g_cs[b*8 + s];
    }
}

// ---------------- host --------------------------------------------------------
extern "C" void kernel_launch(void* const* d_in, const int* in_sizes, int n_in,
                              void* d_out, int out_size) {
    const float* inputs     = (const float*)d_in[0];
    const float* init_noise = (const float*)d_in[1];
    const float* mu         = (const float*)d_in[2];
    const float* sigma_raw  = (const float*)d_in[3];
    const float* ln_in_g    = (const float*)d_in[4];
    const float* ln_in_b    = (const float*)d_in[5];
    const float* ln_s_g     = (const float*)d_in[6];
    const float* ln_s_b     = (const float*)d_in[7];
    const float* ln_m_g     = (const float*)d_in[8];
    const float* ln_m_b     = (const float*)d_in[9];
    const float* wq         = (const float*)d_in[10];
    const float* bq         = (const float*)d_in[11];
    const float* wk         = (const float*)d_in[12];
    const float* bk         = (const float*)d_in[13];
    const float* wv         = (const float*)d_in[14];
    const float* bv         = (const float*)d_in[15];
    const float* w_ih       = (const float*)d_in[16];
    const float* w_hh       = (const float*)d_in[17];
    const float* b_ih       = (const float*)d_in[18];
    const float* b_hh       = (const float*)d_in[19];
    const float* w1         = (const float*)d_in[20];
    const float* b1         = (const float*)d_in[21];
    const float* w2         = (const float*)d_in[22];
    const float* b2         = (const float*)d_in[23];
    float* out = (float*)d_out;

    k_prep_wkb<<<1, 256>>>(wk, ln_in_b, bk);
    k_prep_M<<<256, 256>>>(wq, wk, bq, ln_in_g);
    k_prep_vec<<<1, 256>>>(wq, bq);
    k_meanvar<<<TOK/8, 256>>>(inputs);

    for (int it = 0; it < 3; ++it) {
        bool last = (it == 2);
        k_qproj4<<<B_, 256>>>(ln_s_g, ln_s_b, it == 0 ? 1 : 0,
                              init_noise, mu, sigma_raw);
        k_attn3<<<dim3(16, B_), 256>>>(inputs, last ? 1 : 0);
        k_gru3<<<B_*4, 256>>>(ln_in_g, ln_in_b, wv, bv,
                              w_ih, w_hh, b_ih, b_hh, ln_m_g, ln_m_b,
                              w1, b1, w2, b2, last ? out : nullptr);
        if (last) k_attn_out<<<(TOK*S_ + 255)/256, 256>>>(out + B_*S_*D_);
    }
}

// round 10
// speedup vs baseline: 1.1545x; 1.0219x over previous
#include <cuda_runtime.h>
#include <cstdint>
#include <math.h>

#define B_   32
#define N_   4096
#define D_   256
#define S_   8
#define H_   512
#define TOK  (B_*N_)      // 131072
#define EPS  1e-5f
#define SCALE 0.0625f     // 256^-0.5

// ---------------- scratch (device globals) ----------------------------------
__device__ float g_mean[TOK];
__device__ float g_rstd[TOK];
__device__ float g_slots[B_*S_*D_];
__device__ float g_p[B_*S_*D_];      // pg = SCALE * g ∘ (q @ wk)
__device__ float g_S1[B_*S_];
__device__ float g_S2[B_*S_];
__device__ float g_attn[TOK*S_];     // last iter only
__device__ float g_cs[B_*S_];
__device__ float g_t1[B_*S_];
__device__ float g_U[B_*S_*D_];
__device__ float g_wkgT[D_*D_];      // wkgT[d][j] = ln_in_g[d]*wk[j][d]
__device__ float g_wkb[D_];          // wk @ ln_in_b + bk

__device__ __forceinline__ float sigmoidf_(float x) { return 1.f / (1.f + expf(-x)); }

// ---------------- prep (merged): transposed g-scaled wk + wkb ---------------
__global__ void k_prep_all(const float* __restrict__ wk, const float* __restrict__ lng,
                           const float* __restrict__ lnb, const float* __restrict__ bk) {
    if (blockIdx.x < 64) {
        __shared__ float tile[32][33];
        int bj = blockIdx.x & 7, bd = blockIdx.x >> 3;
        int j0 = bj * 32, d0 = bd * 32;
        int tx = threadIdx.x & 31, ty = threadIdx.x >> 5;
        #pragma unroll
        for (int r = 0; r < 4; r++)
            tile[ty + 8*r][tx] = wk[(size_t)(j0 + ty + 8*r) * 256 + d0 + tx];
        __syncthreads();
        #pragma unroll
        for (int r = 0; r < 4; r++) {
            int d = d0 + ty + 8*r;
            g_wkgT[(size_t)d * 256 + j0 + tx] = lng[d] * tile[tx][ty + 8*r];
        }
    } else {
        int j = threadIdx.x;
        const float* wr = wk + (size_t)j * 256;
        float acc = bk[j];
        #pragma unroll 4
        for (int e = 0; e < 256; e += 4) {
            float4 w4 = *(const float4*)&wr[e];
            float4 b4 = *(const float4*)&lnb[e];
            acc += w4.x*b4.x + w4.y*b4.y + w4.z*b4.z + w4.w*b4.w;
        }
        g_wkb[j] = acc;
    }
}

// ---------------- K1: per-token mean/rstd ------------------------------------
__global__ void k_meanvar(const float* __restrict__ x) {
    int warp = threadIdx.x >> 5, lane = threadIdx.x & 31;
    int tok = blockIdx.x * 8 + warp;
    const float4* row = (const float4*)(x + (size_t)tok * D_);
    float4 a = row[lane*2], b = row[lane*2+1];
    float s = a.x+a.y+a.z+a.w + b.x+b.y+b.z+b.w;
    float q = a.x*a.x+a.y*a.y+a.z*a.z+a.w*a.w + b.x*b.x+b.y*b.y+b.z*b.z+b.w*b.w;
    #pragma unroll
    for (int o = 16; o; o >>= 1) {
        s += __shfl_xor_sync(0xffffffffu, s, o);
        q += __shfl_xor_sync(0xffffffffu, q, o);
    }
    if (lane == 0) {
        float m = s * (1.f/256.f);
        g_mean[tok] = m;
        g_rstd[tok] = rsqrtf(q * (1.f/256.f) - m*m + EPS);
    }
}

// ---------------- K4: per-batch q proj + pg/S1/S2 + zeroing (+slot init) ----
__global__ void __launch_bounds__(256) k_qproj3(
    const float* __restrict__ g, const float* __restrict__ bln,
    const float* __restrict__ wq, const float* __restrict__ bq,
    int init,
    const float* __restrict__ noise, const float* __restrict__ mu,
    const float* __restrict__ sigma_raw)
{
    __shared__ __align__(16) float sa[8][256];
    __shared__ __align__(16) float sq[8][256];
    __shared__ float sm[8], sr[8];
    __shared__ float red1[8][8], red2[8][8];
    int b = blockIdx.x, t = threadIdx.x;
    int w = t >> 5, lane = t & 31;

    if (init) {
        float sr_ = sigma_raw[t];
        float sp = (sr_ > 20.f) ? sr_ : log1pf(expf(sr_));
        float muv = mu[t];
        #pragma unroll
        for (int s = 0; s < 8; s++) {
            float v = muv + sp * noise[(b*8+s)*256 + t];
            sa[s][t] = v;
            g_slots[(b*8+s)*256 + t] = v;
            g_U[(b*8+s)*256 + t] = 0.f;
        }
    } else {
        #pragma unroll
        for (int s = 0; s < 8; s++) {
            g_U[(b*8+s)*256 + t] = 0.f;
            sa[s][t] = g_slots[(b*8+s)*256 + t];
        }
    }
    if (t < 8) { g_cs[b*8 + t] = 0.f; g_t1[b*8 + t] = 0.f; }
    __syncthreads();

    {
        float s1 = 0.f, s2 = 0.f;
        #pragma unroll
        for (int e = 0; e < 8; e++) {
            float v = sa[w][lane + e*32];
            s1 += v; s2 += v*v;
        }
        #pragma unroll
        for (int o = 16; o; o >>= 1) {
            s1 += __shfl_xor_sync(0xffffffffu, s1, o);
            s2 += __shfl_xor_sync(0xffffffffu, s2, o);
        }
        if (lane == 0) {
            float m = s1 * (1.f/256.f);
            sm[w] = m;
            sr[w] = rsqrtf(s2 * (1.f/256.f) - m*m + EPS);
        }
    }
    __syncthreads();
    float gt = g[t], bt = bln[t];
    #pragma unroll
    for (int s = 0; s < 8; s++)
        sa[s][t] = (sa[s][t] - sm[s]) * sr[s] * gt + bt;
    __syncthreads();

    // q[s][t] = sa[s]·wq[t,:] + bq[t]
    {
        float acc[8] = {0,0,0,0,0,0,0,0};
        const float* wr = wq + (size_t)t * 256;
        #pragma unroll 2
        for (int e = 0; e < 256; e += 4) {
            float4 w4 = *(const float4*)&wr[e];
            #pragma unroll
            for (int s = 0; s < 8; s++) {
                float4 a4 = *(const float4*)&sa[s][e];
                acc[s] += w4.x*a4.x + w4.y*a4.y + w4.z*a4.z + w4.w*a4.w;
            }
        }
        float bqt = bq[t];
        #pragma unroll
        for (int s = 0; s < 8; s++) sq[s][t] = acc[s] + bqt;
    }
    __syncthreads();

    // pg[s][t] = SCALE * q[s]·wkgT[t,:]; S1 = sum_t pg; S2 = SCALE * q·wkb
    float pgv[8] = {0,0,0,0,0,0,0,0};
    {
        const float* wr = g_wkgT + (size_t)t * 256;
        #pragma unroll 2
        for (int e = 0; e < 256; e += 4) {
            float4 w4 = *(const float4*)&wr[e];
            #pragma unroll
            for (int s = 0; s < 8; s++) {
                float4 q4 = *(const float4*)&sq[s][e];
                pgv[s] += w4.x*q4.x + w4.y*q4.y + w4.z*q4.z + w4.w*q4.w;
            }
        }
    }
    float wkbt = g_wkb[t];
    float p2[8];
    #pragma unroll
    for (int s = 0; s < 8; s++) {
        pgv[s] *= SCALE;
        g_p[(b*8+s)*256 + t] = pgv[s];
        p2[s] = sq[s][t] * wkbt;
    }
    #pragma unroll
    for (int s = 0; s < 8; s++) {
        float v1 = pgv[s], v2 = p2[s];
        #pragma unroll
        for (int o = 16; o; o >>= 1) {
            v1 += __shfl_xor_sync(0xffffffffu, v1, o);
            v2 += __shfl_xor_sync(0xffffffffu, v2, o);
        }
        if (lane == 0) { red1[s][w] = v1; red2[s][w] = v2; }
    }
    __syncthreads();
    if (t < 8) {
        float a1 = 0.f, a2 = 0.f;
        #pragma unroll
        for (int i = 0; i < 8; i++) { a1 += red1[t][i]; a2 += red2[t][i]; }
        g_S1[b*8 + t] = a1;
        g_S2[b*8 + t] = a2 * SCALE;
    }
}

// ---------------- K5: fused attn, thread-per-(token,slot), no big reductions -
#define XP 260     // padded row pitch (floats)

__global__ void __launch_bounds__(256) k_attn4(const float* __restrict__ x,
                                               int store_attn) {
    __shared__ float sX[32*XP];              // 33.3 KB x tile
    __shared__ float sP[8*XP];               // 8.3 KB pg
    __shared__ __align__(16) float sA[32][8];
    __shared__ float sCS[8][33], sT1[8][33];

    int b = blockIdx.y, chunk = blockIdx.x;
    int t = threadIdx.x;
    int loc = t >> 3, s = t & 7;             // token-in-tile, slot

    // load pg (8 x 256) into smem
    const float* pb = g_p + b*S_*D_;
    #pragma unroll
    for (int idx = t; idx < 2048; idx += 256) {
        int ss = idx >> 8, e = idx & 255;
        sP[ss*XP + e] = pb[idx];
    }
    float S1l = g_S1[b*8 + s];
    float S2l = g_S2[b*8 + s];

    float u[8] = {0,0,0,0,0,0,0,0};
    float csA = 0.f, t1A = 0.f;
    int base_tok = b*N_ + chunk*256;
    __syncthreads();

    for (int sub = 0; sub < 8; sub++) {
        int tok0 = base_tok + sub*32;
        // stage x tile (32 x 256) coalesced
        #pragma unroll
        for (int k = 0; k < 8; k++) {
            int c = t + k*256;                 // float4 chunk 0..2047
            int row = c >> 6, col = (c & 63) * 4;
            float4 v = *(const float4*)(x + (size_t)(tok0 + row)*256 + col);
            *(float4*)&sX[row*XP + col] = v;
        }
        __syncthreads();

        // full dot for (loc, s) from smem — conflict-free
        float a0 = 0.f, a1 = 0.f, a2 = 0.f, a3 = 0.f;
        const float* xr = sX + loc*XP;
        const float* pr = sP + s*XP;
        #pragma unroll 8
        for (int e = 0; e < 256; e += 4) {
            float4 xv = *(const float4*)&xr[e];
            float4 pv = *(const float4*)&pr[e];
            a0 += xv.x*pv.x; a1 += xv.y*pv.y;
            a2 += xv.z*pv.z; a3 += xv.w*pv.w;
        }
        float dot = (a0 + a1) + (a2 + a3);

        int n = tok0 + loc;
        float r = g_rstd[n], m = g_mean[n];   // 8-lane broadcast LDG
        float rm = r * m;
        float lg = r*dot - rm*S1l + S2l;
        // softmax across 8 adjacent lanes (slots)
        float mx = lg;
        mx = fmaxf(mx, __shfl_xor_sync(0xffffffffu, mx, 1));
        mx = fmaxf(mx, __shfl_xor_sync(0xffffffffu, mx, 2));
        mx = fmaxf(mx, __shfl_xor_sync(0xffffffffu, mx, 4));
        float e = expf(lg - mx);
        float sum = e;
        sum += __shfl_xor_sync(0xffffffffu, sum, 1);
        sum += __shfl_xor_sync(0xffffffffu, sum, 2);
        sum += __shfl_xor_sync(0xffffffffu, sum, 4);
        float a = e / sum + 1e-8f;
        csA += a;
        t1A += a * rm;
        sA[loc][s] = a * r;
        if (store_attn) g_attn[(size_t)n*8 + s] = a;
        __syncthreads();

        // pass 2: U accumulation; sX banks (4i+t)%32 distinct, sA broadcast
        #pragma unroll 8
        for (int i = 0; i < 32; i++) {
            float xv = sX[i*XP + t];
            float4 p0 = *(const float4*)&sA[i][0];
            float4 p1 = *(const float4*)&sA[i][4];
            u[0] += p0.x*xv; u[1] += p0.y*xv; u[2] += p0.z*xv; u[3] += p0.w*xv;
            u[4] += p1.x*xv; u[5] += p1.y*xv; u[6] += p1.z*xv; u[7] += p1.w*xv;
        }
        __syncthreads();
    }

    #pragma unroll
    for (int ss = 0; ss < 8; ss++)
        atomicAdd(&g_U[(b*8+ss)*256 + t], u[ss]);
    sCS[s][loc] = csA;
    sT1[s][loc] = t1A;
    __syncthreads();
    if (t < 8) {
        float a = 0.f;
        #pragma unroll
        for (int i = 0; i < 32; i++) a += sCS[t][i];
        atomicAdd(&g_cs[b*8 + t], a);
    } else if (t < 16) {
        int ss = t - 8;
        float a = 0.f;
        #pragma unroll
        for (int i = 0; i < 32; i++) a += sT1[ss][i];
        atomicAdd(&g_t1[b*8 + ss], a);
    }
}

// ---------------- K7: GRU + LN + MLP, block per (batch, slot-pair) ----------
__global__ void __launch_bounds__(256) k_gru3(
    const float* __restrict__ lng_in, const float* __restrict__ lnb_in,
    const float* __restrict__ wv,   const float* __restrict__ bv,
    const float* __restrict__ w_ih, const float* __restrict__ w_hh,
    const float* __restrict__ b_ih, const float* __restrict__ b_hh,
    const float* __restrict__ lng,  const float* __restrict__ lnb,
    const float* __restrict__ w1,   const float* __restrict__ b1,
    const float* __restrict__ w2,   const float* __restrict__ b2,
    float* __restrict__ out_slots)
{
    __shared__ __align__(16) float szn[2][256];
    __shared__ __align__(16) float su[2][256];
    __shared__ __align__(16) float sh[2][256];
    __shared__ __align__(16) float sa[2][256];
    __shared__ __align__(16) float sh1[2][512];
    __shared__ float sm[2], sr2[2];

    int b = blockIdx.x >> 2;
    int p = blockIdx.x & 3;
    int row0 = b*8 + p*2;
    int t = threadIdx.x;

    #pragma unroll
    for (int sl = 0; sl < 2; sl++) {
        int row = row0 + sl;
        float csv = g_cs[row], t1v = g_t1[row];
        float Ut = g_U[row*256 + t];
        szn[sl][t] = lng_in[t] * (Ut - t1v) / csv + lnb_in[t];
        sh[sl][t] = g_slots[row*256 + t];
    }
    __syncthreads();

    {
        float a0 = 0.f, a1 = 0.f;
        const float* wr = wv + (size_t)t * 256;
        #pragma unroll 2
        for (int e = 0; e < 256; e += 4) {
            float4 w4 = *(const float4*)&wr[e];
            float4 z0 = *(const float4*)&szn[0][e];
            float4 z1 = *(const float4*)&szn[1][e];
            a0 += w4.x*z0.x + w4.y*z0.y + w4.z*z0.z + w4.w*z0.w;
            a1 += w4.x*z1.x + w4.y*z1.y + w4.z*z1.z + w4.w*z1.w;
        }
        float bvt = bv[t];
        su[0][t] = a0 + bvt;
        su[1][t] = a1 + bvt;
    }
    __syncthreads();

    float xr[2], xz[2], xn[2], hr[2], hz[2], hn[2];
    #pragma unroll
    for (int sl = 0; sl < 2; sl++) {
        xr[sl] = b_ih[t]; xz[sl] = b_ih[256+t]; xn[sl] = b_ih[512+t];
        hr[sl] = b_hh[t]; hz[sl] = b_hh[256+t]; hn[sl] = b_hh[512+t];
    }
    const float* wir = w_ih + (size_t)t*256;
    const float* wiz = w_ih + (size_t)(256+t)*256;
    const float* win = w_ih + (size_t)(512+t)*256;
    const float* whr = w_hh + (size_t)t*256;
    const float* whz = w_hh + (size_t)(256+t)*256;
    const float* whn = w_hh + (size_t)(512+t)*256;

    #pragma unroll 2
    for (int e = 0; e < 256; e += 4) {
        float4 wr4 = *(const float4*)&wir[e];
        float4 wz4 = *(const float4*)&wiz[e];
        float4 wn4 = *(const float4*)&win[e];
        float4 vr4 = *(const float4*)&whr[e];
        float4 vz4 = *(const float4*)&whz[e];
        float4 vn4 = *(const float4*)&whn[e];
        #pragma unroll
        for (int sl = 0; sl < 2; sl++) {
            float4 u4 = *(const float4*)&su[sl][e];
            float4 h4 = *(const float4*)&sh[sl][e];
            xr[sl] += wr4.x*u4.x + wr4.y*u4.y + wr4.z*u4.z + wr4.w*u4.w;
            xz[sl] += wz4.x*u4.x + wz4.y*u4.y + wz4.z*u4.z + wz4.w*u4.w;
            xn[sl] += wn4.x*u4.x + wn4.y*u4.y + wn4.z*u4.z + wn4.w*u4.w;
            hr[sl] += vr4.x*h4.x + vr4.y*h4.y + vr4.z*h4.z + vr4.w*h4.w;
            hz[sl] += vz4.x*h4.x + vz4.y*h4.y + vz4.z*h4.z + vz4.w*h4.w;
            hn[sl] += vn4.x*h4.x + vn4.y*h4.y + vn4.z*h4.z + vn4.w*h4.w;
        }
    }
    float hnew[2];
    #pragma unroll
    for (int sl = 0; sl < 2; sl++) {
        float r = sigmoidf_(xr[sl] + hr[sl]);
        float z = sigmoidf_(xz[sl] + hz[sl]);
        float nn = tanhf(xn[sl] + r*hn[sl]);
        hnew[sl] = (1.f - z)*nn + z*sh[sl][t];
    }
    __syncthreads();
    su[0][t] = hnew[0]; su[1][t] = hnew[1];
    __syncthreads();
    int w = t >> 5, lane = t & 31;
    if (w < 2) {
        float s1 = 0.f, s2 = 0.f;
        #pragma unroll
        for (int e = 0; e < 8; e++) {
            float v = su[w][lane + e*32];
            s1 += v; s2 += v*v;
        }
        #pragma unroll
        for (int o = 16; o; o >>= 1) {
            s1 += __shfl_xor_sync(0xffffffffu, s1, o);
            s2 += __shfl_xor_sync(0xffffffffu, s2, o);
        }
        if (lane == 0) {
            float m = s1 * (1.f/256.f);
            sm[w] = m;
            sr2[w] = rsqrtf(s2 * (1.f/256.f) - m*m + EPS);
        }
    }
    __syncthreads();
    float gt = lng[t], bt = lnb[t];
    sa[0][t] = (hnew[0] - sm[0]) * sr2[0] * gt + bt;
    sa[1][t] = (hnew[1] - sm[1]) * sr2[1] * gt + bt;
    __syncthreads();

    float a1[2] = {b1[t], b1[t]};
    float a2[2] = {b1[256+t], b1[256+t]};
    const float* w1a = w1 + (size_t)t*256;
    const float* w1b = w1 + (size_t)(256+t)*256;
    #pragma unroll 2
    for (int e = 0; e < 256; e += 4) {
        float4 wa = *(const float4*)&w1a[e];
        float4 wb = *(const float4*)&w1b[e];
        #pragma unroll
        for (int sl = 0; sl < 2; sl++) {
            float4 s4 = *(const float4*)&sa[sl][e];
            a1[sl] += wa.x*s4.x + wa.y*s4.y + wa.z*s4.z + wa.w*s4.w;
            a2[sl] += wb.x*s4.x + wb.y*s4.y + wb.z*s4.z + wb.w*s4.w;
        }
    }
    sh1[0][t] = fmaxf(a1[0], 0.f); sh1[0][256+t] = fmaxf(a2[0], 0.f);
    sh1[1][t] = fmaxf(a1[1], 0.f); sh1[1][256+t] = fmaxf(a2[1], 0.f);
    __syncthreads();

    float o[2] = {b2[t], b2[t]};
    const float* w2r = w2 + (size_t)t*512;
    #pragma unroll 2
    for (int e = 0; e < 512; e += 4) {
        float4 w4 = *(const float4*)&w2r[e];
        #pragma unroll
        for (int sl = 0; sl < 2; sl++) {
            float4 h4 = *(const float4*)&sh1[sl][e];
            o[sl] += w4.x*h4.x + w4.y*h4.y + w4.z*h4.z + w4.w*h4.w;
        }
    }
    #pragma unroll
    for (int sl = 0; sl < 2; sl++) {
        float res = hnew[sl] + o[sl];
        g_slots[(row0+sl)*256 + t] = res;
        if (out_slots) out_slots[(row0+sl)*256 + t] = res;
    }
}

// ---------------- K8: final attn normalize to d_out --------------------------
__global__ void k_attn_out(float* __restrict__ dst) {
    int i = blockIdx.x*blockDim.x + threadIdx.x;
    if (i < TOK*S_) {
        int s = i & 7;
        int b = i >> 15;
        dst[i] = g_attn[i] / g_cs[b*8 + s];
    }
}

// ---------------- host --------------------------------------------------------
extern "C" void kernel_launch(void* const* d_in, const int* in_sizes, int n_in,
                              void* d_out, int out_size) {
    const float* inputs     = (const float*)d_in[0];
    const float* init_noise = (const float*)d_in[1];
    const float* mu         = (const float*)d_in[2];
    const float* sigma_raw  = (const float*)d_in[3];
    const float* ln_in_g    = (const float*)d_in[4];
    const float* ln_in_b    = (const float*)d_in[5];
    const float* ln_s_g     = (const float*)d_in[6];
    const float* ln_s_b     = (const float*)d_in[7];
    const float* ln_m_g     = (const float*)d_in[8];
    const float* ln_m_b     = (const float*)d_in[9];
    const float* wq         = (const float*)d_in[10];
    const float* bq         = (const float*)d_in[11];
    const float* wk         = (const float*)d_in[12];
    const float* bk         = (const float*)d_in[13];
    const float* wv         = (const float*)d_in[14];
    const float* bv         = (const float*)d_in[15];
    const float* w_ih       = (const float*)d_in[16];
    const float* w_hh       = (const float*)d_in[17];
    const float* b_ih       = (const float*)d_in[18];
    const float* b_hh       = (const float*)d_in[19];
    const float* w1         = (const float*)d_in[20];
    const float* b1         = (const float*)d_in[21];
    const float* w2         = (const float*)d_in[22];
    const float* b2         = (const float*)d_in[23];
    float* out = (float*)d_out;

    k_prep_all<<<65, 256>>>(wk, ln_in_g, ln_in_b, bk);
    k_meanvar<<<TOK/8, 256>>>(inputs);

    for (int it = 0; it < 3; ++it) {
        bool last = (it == 2);
        k_qproj3<<<B_, 256>>>(ln_s_g, ln_s_b, wq, bq,
                              it == 0 ? 1 : 0, init_noise, mu, sigma_raw);
        k_attn4<<<dim3(16, B_), 256>>>(inputs, last ? 1 : 0);
        k_gru3<<<B_*4, 256>>>(ln_in_g, ln_in_b, wv, bv,
                              w_ih, w_hh, b_ih, b_hh, ln_m_g, ln_m_b,
                              w1, b1, w2, b2, last ? out : nullptr);
        if (last) k_attn_out<<<(TOK*S_ + 255)/256, 256>>>(out + B_*S_*D_);
    }
}

// round 11
// speedup vs baseline: 1.2087x; 1.0469x over previous
#include <cuda_runtime.h>
#include <cstdint>
#include <math.h>

#define B_   32
#define N_   4096
#define D_   256
#define S_   8
#define H_   512
#define TOK  (B_*N_)      // 131072
#define EPS  1e-5f
#define SCALE 0.0625f     // 256^-0.5

// ---------------- scratch (device globals) ----------------------------------
__device__ float g_mean[TOK];
__device__ float g_rstd[TOK];
__device__ float g_slots[B_*S_*D_];
__device__ float g_p[B_*S_*D_];      // pg = SCALE * g ∘ (q @ wk)
__device__ float g_S1[B_*S_];
__device__ float g_S2[B_*S_];
__device__ float g_attn[TOK*S_];     // last iter only
__device__ float g_cs[B_*S_];
__device__ float g_t1[B_*S_];
__device__ float g_U[B_*S_*D_];
__device__ float g_wkgT[D_*D_];      // wkgT[d][j] = ln_in_g[d]*wk[j][d]
__device__ float g_wkb[D_];          // wk @ ln_in_b + bk

__device__ __forceinline__ float sigmoidf_(float x) { return 1.f / (1.f + expf(-x)); }

// ---------------- prep (merged): transposed g-scaled wk + wkb ---------------
__global__ void k_prep_all(const float* __restrict__ wk, const float* __restrict__ lng,
                           const float* __restrict__ lnb, const float* __restrict__ bk) {
    if (blockIdx.x < 64) {
        __shared__ float tile[32][33];
        int bj = blockIdx.x & 7, bd = blockIdx.x >> 3;
        int j0 = bj * 32, d0 = bd * 32;
        int tx = threadIdx.x & 31, ty = threadIdx.x >> 5;
        #pragma unroll
        for (int r = 0; r < 4; r++)
            tile[ty + 8*r][tx] = wk[(size_t)(j0 + ty + 8*r) * 256 + d0 + tx];
        __syncthreads();
        #pragma unroll
        for (int r = 0; r < 4; r++) {
            int d = d0 + ty + 8*r;
            g_wkgT[(size_t)d * 256 + j0 + tx] = lng[d] * tile[tx][ty + 8*r];
        }
    } else {
        int j = threadIdx.x;
        const float* wr = wk + (size_t)j * 256;
        float acc = bk[j];
        #pragma unroll 4
        for (int e = 0; e < 256; e += 4) {
            float4 w4 = *(const float4*)&wr[e];
            float4 b4 = *(const float4*)&lnb[e];
            acc += w4.x*b4.x + w4.y*b4.y + w4.z*b4.z + w4.w*b4.w;
        }
        g_wkb[j] = acc;
    }
}

// ---------------- K1: per-token mean/rstd ------------------------------------
__global__ void k_meanvar(const float* __restrict__ x) {
    int warp = threadIdx.x >> 5, lane = threadIdx.x & 31;
    int tok = blockIdx.x * 8 + warp;
    const float4* row = (const float4*)(x + (size_t)tok * D_);
    float4 a = row[lane*2], b = row[lane*2+1];
    float s = a.x+a.y+a.z+a.w + b.x+b.y+b.z+b.w;
    float q = a.x*a.x+a.y*a.y+a.z*a.z+a.w*a.w + b.x*b.x+b.y*b.y+b.z*b.z+b.w*b.w;
    #pragma unroll
    for (int o = 16; o; o >>= 1) {
        s += __shfl_xor_sync(0xffffffffu, s, o);
        q += __shfl_xor_sync(0xffffffffu, q, o);
    }
    if (lane == 0) {
        float m = s * (1.f/256.f);
        g_mean[tok] = m;
        g_rstd[tok] = rsqrtf(q * (1.f/256.f) - m*m + EPS);
    }
}

// ---------------- K4: qproj (iteration 0 only: init slots + pg/S1/S2) -------
__global__ void __launch_bounds__(256) k_qproj3(
    const float* __restrict__ g, const float* __restrict__ bln,
    const float* __restrict__ wq, const float* __restrict__ bq,
    const float* __restrict__ noise, const float* __restrict__ mu,
    const float* __restrict__ sigma_raw)
{
    __shared__ __align__(16) float sa[8][256];
    __shared__ __align__(16) float sq[8][256];
    __shared__ float sm[8], sr[8];
    __shared__ float red1[8][8], red2[8][8];
    int b = blockIdx.x, t = threadIdx.x;
    int w = t >> 5, lane = t & 31;

    float sr_ = sigma_raw[t];
    float sp = (sr_ > 20.f) ? sr_ : log1pf(expf(sr_));
    float muv = mu[t];
    #pragma unroll
    for (int s = 0; s < 8; s++) {
        float v = muv + sp * noise[(b*8+s)*256 + t];
        sa[s][t] = v;
        g_slots[(b*8+s)*256 + t] = v;
        g_U[(b*8+s)*256 + t] = 0.f;
    }
    if (t < 8) { g_cs[b*8 + t] = 0.f; g_t1[b*8 + t] = 0.f; }
    __syncthreads();

    {
        float s1 = 0.f, s2 = 0.f;
        #pragma unroll
        for (int e = 0; e < 8; e++) {
            float v = sa[w][lane + e*32];
            s1 += v; s2 += v*v;
        }
        #pragma unroll
        for (int o = 16; o; o >>= 1) {
            s1 += __shfl_xor_sync(0xffffffffu, s1, o);
            s2 += __shfl_xor_sync(0xffffffffu, s2, o);
        }
        if (lane == 0) {
            float m = s1 * (1.f/256.f);
            sm[w] = m;
            sr[w] = rsqrtf(s2 * (1.f/256.f) - m*m + EPS);
        }
    }
    __syncthreads();
    float gt = g[t], bt = bln[t];
    #pragma unroll
    for (int s = 0; s < 8; s++)
        sa[s][t] = (sa[s][t] - sm[s]) * sr[s] * gt + bt;
    __syncthreads();

    {
        float acc[8] = {0,0,0,0,0,0,0,0};
        const float* wr = wq + (size_t)t * 256;
        #pragma unroll 2
        for (int e = 0; e < 256; e += 4) {
            float4 w4 = *(const float4*)&wr[e];
            #pragma unroll
            for (int s = 0; s < 8; s++) {
                float4 a4 = *(const float4*)&sa[s][e];
                acc[s] += w4.x*a4.x + w4.y*a4.y + w4.z*a4.z + w4.w*a4.w;
            }
        }
        float bqt = bq[t];
        #pragma unroll
        for (int s = 0; s < 8; s++) sq[s][t] = acc[s] + bqt;
    }
    __syncthreads();

    float pgv[8] = {0,0,0,0,0,0,0,0};
    {
        const float* wr = g_wkgT + (size_t)t * 256;
        #pragma unroll 2
        for (int e = 0; e < 256; e += 4) {
            float4 w4 = *(const float4*)&wr[e];
            #pragma unroll
            for (int s = 0; s < 8; s++) {
                float4 q4 = *(const float4*)&sq[s][e];
                pgv[s] += w4.x*q4.x + w4.y*q4.y + w4.z*q4.z + w4.w*q4.w;
            }
        }
    }
    float wkbt = g_wkb[t];
    float p2[8];
    #pragma unroll
    for (int s = 0; s < 8; s++) {
        pgv[s] *= SCALE;
        g_p[(b*8+s)*256 + t] = pgv[s];
        p2[s] = sq[s][t] * wkbt;
    }
    #pragma unroll
    for (int s = 0; s < 8; s++) {
        float v1 = pgv[s], v2 = p2[s];
        #pragma unroll
        for (int o = 16; o; o >>= 1) {
            v1 += __shfl_xor_sync(0xffffffffu, v1, o);
            v2 += __shfl_xor_sync(0xffffffffu, v2, o);
        }
        if (lane == 0) { red1[s][w] = v1; red2[s][w] = v2; }
    }
    __syncthreads();
    if (t < 8) {
        float a1 = 0.f, a2 = 0.f;
        #pragma unroll
        for (int i = 0; i < 8; i++) { a1 += red1[t][i]; a2 += red2[t][i]; }
        g_S1[b*8 + t] = a1;
        g_S2[b*8 + t] = a2 * SCALE;
    }
}

// ---------------- K5: fused attn (register pg, no-max softmax) --------------
// grid (32 chunks, 32 batches), 128 tokens/CTA
__global__ void __launch_bounds__(256, 2) k_attn5(const float* __restrict__ x,
                                                  int store_attn) {
    __shared__ __align__(16) float sA[32][8];
    __shared__ float scs[8][8], st1[8][8];
    int b = blockIdx.y, chunk = blockIdx.x;
    int t = threadIdx.x;
    int wid = t >> 5, lane = t & 31;
    int slot = (lane >> 2) & 7;

    float pg[8][8];
    {
        const float* pb = g_p + b*S_*D_;
        #pragma unroll
        for (int s = 0; s < 8; s++) {
            float4 a = *(const float4*)&pb[s*256 + lane*8];
            float4 c = *(const float4*)&pb[s*256 + lane*8 + 4];
            pg[s][0]=a.x; pg[s][1]=a.y; pg[s][2]=a.z; pg[s][3]=a.w;
            pg[s][4]=c.x; pg[s][5]=c.y; pg[s][6]=c.z; pg[s][7]=c.w;
        }
    }
    float S1l = g_S1[b*8 + slot];
    float S2l = g_S2[b*8 + slot];

    float u[8]  = {0,0,0,0,0,0,0,0};
    float csA = 0.f, t1A = 0.f;
    int base_tok = b*N_ + chunk*128;

    for (int sub = 0; sub < 4; sub++) {
        int sub0 = sub * 32;
        // software-pipelined x load
        int n0 = base_tok + sub0 + wid*4;
        const float* xr0 = x + (size_t)n0*256 + lane*8;
        float4 xa = *(const float4*)xr0;
        float4 xb = *(const float4*)(xr0 + 4);
        #pragma unroll
        for (int i = 0; i < 4; i++) {
            int loc = sub0 + wid*4 + i;
            int n = base_tok + loc;
            float4 cxa = xa, cxb = xb;
            if (i < 3) {
                const float* xr = x + (size_t)(n+1)*256 + lane*8;
                xa = *(const float4*)xr;
                xb = *(const float4*)(xr + 4);
            }
            float dt[8];
            #pragma unroll
            for (int s = 0; s < 8; s++) {
                dt[s] = cxa.x*pg[s][0] + cxa.y*pg[s][1] + cxa.z*pg[s][2] + cxa.w*pg[s][3]
                      + cxb.x*pg[s][4] + cxb.y*pg[s][5] + cxb.z*pg[s][6] + cxb.w*pg[s][7];
            }
            // halving-tree reduction (16 shfl)
            float e0, e1, e2, e3;
            {
                float r0 = __shfl_xor_sync(0xffffffffu, dt[0], 16);
                float r1 = __shfl_xor_sync(0xffffffffu, dt[1], 16);
                float r2 = __shfl_xor_sync(0xffffffffu, dt[2], 16);
                float r3 = __shfl_xor_sync(0xffffffffu, dt[3], 16);
                float r4 = __shfl_xor_sync(0xffffffffu, dt[4], 16);
                float r5 = __shfl_xor_sync(0xffffffffu, dt[5], 16);
                float r6 = __shfl_xor_sync(0xffffffffu, dt[6], 16);
                float r7 = __shfl_xor_sync(0xffffffffu, dt[7], 16);
                bool hi = (lane & 16) != 0;
                e0 = hi ? (dt[4]+r4) : (dt[0]+r0);
                e1 = hi ? (dt[5]+r5) : (dt[1]+r1);
                e2 = hi ? (dt[6]+r6) : (dt[2]+r2);
                e3 = hi ? (dt[7]+r7) : (dt[3]+r3);
            }
            float f0, f1;
            {
                float r0 = __shfl_xor_sync(0xffffffffu, e0, 8);
                float r1 = __shfl_xor_sync(0xffffffffu, e1, 8);
                float r2 = __shfl_xor_sync(0xffffffffu, e2, 8);
                float r3 = __shfl_xor_sync(0xffffffffu, e3, 8);
                bool hi = (lane & 8) != 0;
                f0 = hi ? (e2+r2) : (e0+r0);
                f1 = hi ? (e3+r3) : (e1+r1);
            }
            float v;
            {
                float r0 = __shfl_xor_sync(0xffffffffu, f0, 4);
                float r1 = __shfl_xor_sync(0xffffffffu, f1, 4);
                bool hi = (lane & 4) != 0;
                v = hi ? (f1+r1) : (f0+r0);
            }
            v += __shfl_xor_sync(0xffffffffu, v, 2);
            v += __shfl_xor_sync(0xffffffffu, v, 1);

            float r = g_rstd[n], m = g_mean[n];
            float rm = r * m;
            float lg = r*v - rm*S1l + S2l;
            // softmax WITHOUT max-subtraction (logits O(1); identical math)
            float e = expf(lg);
            float sum = e;
            sum += __shfl_xor_sync(0xffffffffu, sum, 4);
            sum += __shfl_xor_sync(0xffffffffu, sum, 8);
            sum += __shfl_xor_sync(0xffffffffu, sum, 16);
            float a = e / sum + 1e-8f;
            float ar = a * r;
            csA += a;
            t1A += a * rm;
            if ((lane & 3) == 0) {
                sA[loc - sub0][slot] = ar;
                if (store_attn) g_attn[(size_t)n*8 + slot] = a;
            }
        }
        __syncthreads();
        const float* xcol = x + (size_t)(base_tok + sub0)*256 + t;
        #pragma unroll 8
        for (int i = 0; i < 32; i++) {
            float xv = xcol[(size_t)i*256];
            float4 p0 = *(const float4*)&sA[i][0];
            float4 p1 = *(const float4*)&sA[i][4];
            u[0] += p0.x*xv; u[1] += p0.y*xv; u[2] += p0.z*xv; u[3] += p0.w*xv;
            u[4] += p1.x*xv; u[5] += p1.y*xv; u[6] += p1.z*xv; u[7] += p1.w*xv;
        }
        __syncthreads();
    }

    #pragma unroll
    for (int s = 0; s < 8; s++)
        atomicAdd(&g_U[(b*8+s)*256 + t], u[s]);
    if (lane == 0) {
        #pragma unroll
        for (int s = 0; s < 8; s++) { scs[wid][s] = 0.f; st1[wid][s] = 0.f; }
    }
    __syncthreads();
    if ((lane & 3) == 0) {
        atomicAdd(&g_cs[b*8 + slot], csA);
        atomicAdd(&g_t1[b*8 + slot], t1A);
    }
}

// ---------------- K7: GRU + LN + MLP (+ fused next-iter qproj) --------------
__global__ void __launch_bounds__(256) k_gruq(
    const float* __restrict__ lng_in, const float* __restrict__ lnb_in,
    const float* __restrict__ wv,   const float* __restrict__ bv,
    const float* __restrict__ w_ih, const float* __restrict__ w_hh,
    const float* __restrict__ b_ih, const float* __restrict__ b_hh,
    const float* __restrict__ lng,  const float* __restrict__ lnb,
    const float* __restrict__ w1,   const float* __restrict__ b1,
    const float* __restrict__ w2,   const float* __restrict__ b2,
    const float* __restrict__ lsg,  const float* __restrict__ lsb,
    const float* __restrict__ wq,   const float* __restrict__ bq,
    int do_qproj, float* __restrict__ out_slots)
{
    __shared__ __align__(16) float szn[2][256];
    __shared__ __align__(16) float su[2][256];
    __shared__ __align__(16) float sh[2][256];
    __shared__ __align__(16) float sa[2][256];
    __shared__ __align__(16) float sh1[2][512];
    __shared__ float sm[2], sr2[2];
    __shared__ float red1[2][8], red2[2][8];

    int b = blockIdx.x >> 2;
    int p = blockIdx.x & 3;
    int row0 = b*8 + p*2;
    int t = threadIdx.x;

    #pragma unroll
    for (int sl = 0; sl < 2; sl++) {
        int row = row0 + sl;
        float csv = g_cs[row], t1v = g_t1[row];
        float Ut = g_U[row*256 + t];
        szn[sl][t] = lng_in[t] * (Ut - t1v) / csv + lnb_in[t];
        sh[sl][t] = g_slots[row*256 + t];
    }
    __syncthreads();

    {
        float a0 = 0.f, a1 = 0.f;
        const float* wr = wv + (size_t)t * 256;
        #pragma unroll 2
        for (int e = 0; e < 256; e += 4) {
            float4 w4 = *(const float4*)&wr[e];
            float4 z0 = *(const float4*)&szn[0][e];
            float4 z1 = *(const float4*)&szn[1][e];
            a0 += w4.x*z0.x + w4.y*z0.y + w4.z*z0.z + w4.w*z0.w;
            a1 += w4.x*z1.x + w4.y*z1.y + w4.z*z1.z + w4.w*z1.w;
        }
        float bvt = bv[t];
        su[0][t] = a0 + bvt;
        su[1][t] = a1 + bvt;
    }
    __syncthreads();

    float xr[2], xz[2], xn[2], hr[2], hz[2], hn[2];
    #pragma unroll
    for (int sl = 0; sl < 2; sl++) {
        xr[sl] = b_ih[t]; xz[sl] = b_ih[256+t]; xn[sl] = b_ih[512+t];
        hr[sl] = b_hh[t]; hz[sl] = b_hh[256+t]; hn[sl] = b_hh[512+t];
    }
    const float* wir = w_ih + (size_t)t*256;
    const float* wiz = w_ih + (size_t)(256+t)*256;
    const float* win = w_ih + (size_t)(512+t)*256;
    const float* whr = w_hh + (size_t)t*256;
    const float* whz = w_hh + (size_t)(256+t)*256;
    const float* whn = w_hh + (size_t)(512+t)*256;

    #pragma unroll 2
    for (int e = 0; e < 256; e += 4) {
        float4 wr4 = *(const float4*)&wir[e];
        float4 wz4 = *(const float4*)&wiz[e];
        float4 wn4 = *(const float4*)&win[e];
        float4 vr4 = *(const float4*)&whr[e];
        float4 vz4 = *(const float4*)&whz[e];
        float4 vn4 = *(const float4*)&whn[e];
        #pragma unroll
        for (int sl = 0; sl < 2; sl++) {
            float4 u4 = *(const float4*)&su[sl][e];
            float4 h4 = *(const float4*)&sh[sl][e];
            xr[sl] += wr4.x*u4.x + wr4.y*u4.y + wr4.z*u4.z + wr4.w*u4.w;
            xz[sl] += wz4.x*u4.x + wz4.y*u4.y + wz4.z*u4.z + wz4.w*u4.w;
            xn[sl] += wn4.x*u4.x + wn4.y*u4.y + wn4.z*u4.z + wn4.w*u4.w;
            hr[sl] += vr4.x*h4.x + vr4.y*h4.y + vr4.z*h4.z + vr4.w*h4.w;
            hz[sl] += vz4.x*h4.x + vz4.y*h4.y + vz4.z*h4.z + vz4.w*h4.w;
            hn[sl] += vn4.x*h4.x + vn4.y*h4.y + vn4.z*h4.z + vn4.w*h4.w;
        }
    }
    float hnew[2];
    #pragma unroll
    for (int sl = 0; sl < 2; sl++) {
        float r = sigmoidf_(xr[sl] + hr[sl]);
        float z = sigmoidf_(xz[sl] + hz[sl]);
        float nn = tanhf(xn[sl] + r*hn[sl]);
        hnew[sl] = (1.f - z)*nn + z*sh[sl][t];
    }
    __syncthreads();
    su[0][t] = hnew[0]; su[1][t] = hnew[1];
    __syncthreads();
    int w = t >> 5, lane = t & 31;
    if (w < 2) {
        float s1 = 0.f, s2 = 0.f;
        #pragma unroll
        for (int e = 0; e < 8; e++) {
            float v = su[w][lane + e*32];
            s1 += v; s2 += v*v;
        }
        #pragma unroll
        for (int o = 16; o; o >>= 1) {
            s1 += __shfl_xor_sync(0xffffffffu, s1, o);
            s2 += __shfl_xor_sync(0xffffffffu, s2, o);
        }
        if (lane == 0) {
            float m = s1 * (1.f/256.f);
            sm[w] = m;
            sr2[w] = rsqrtf(s2 * (1.f/256.f) - m*m + EPS);
        }
    }
    __syncthreads();
    float gt = lng[t], bt = lnb[t];
    sa[0][t] = (hnew[0] - sm[0]) * sr2[0] * gt + bt;
    sa[1][t] = (hnew[1] - sm[1]) * sr2[1] * gt + bt;
    __syncthreads();

    float a1[2] = {b1[t], b1[t]};
    float a2[2] = {b1[256+t], b1[256+t]};
    const float* w1a = w1 + (size_t)t*256;
    const float* w1b = w1 + (size_t)(256+t)*256;
    #pragma unroll 2
    for (int e = 0; e < 256; e += 4) {
        float4 wa = *(const float4*)&w1a[e];
        float4 wb = *(const float4*)&w1b[e];
        #pragma unroll
        for (int sl = 0; sl < 2; sl++) {
            float4 s4 = *(const float4*)&sa[sl][e];
            a1[sl] += wa.x*s4.x + wa.y*s4.y + wa.z*s4.z + wa.w*s4.w;
            a2[sl] += wb.x*s4.x + wb.y*s4.y + wb.z*s4.z + wb.w*s4.w;
        }
    }
    sh1[0][t] = fmaxf(a1[0], 0.f); sh1[0][256+t] = fmaxf(a2[0], 0.f);
    sh1[1][t] = fmaxf(a1[1], 0.f); sh1[1][256+t] = fmaxf(a2[1], 0.f);
    __syncthreads();

    float o[2] = {b2[t], b2[t]};
    const float* w2r = w2 + (size_t)t*512;
    #pragma unroll 2
    for (int e = 0; e < 512; e += 4) {
        float4 w4 = *(const float4*)&w2r[e];
        #pragma unroll
        for (int sl = 0; sl < 2; sl++) {
            float4 h4 = *(const float4*)&sh1[sl][e];
            o[sl] += w4.x*h4.x + w4.y*h4.y + w4.z*h4.z + w4.w*h4.w;
        }
    }
    float res[2];
    #pragma unroll
    for (int sl = 0; sl < 2; sl++) {
        res[sl] = hnew[sl] + o[sl];
        g_slots[(row0+sl)*256 + t] = res[sl];
        if (out_slots) out_slots[(row0+sl)*256 + t] = res[sl];
    }

    if (!do_qproj) return;

    // ======== fused qproj for next iteration (2 slots) ========
    __syncthreads();
    sh[0][t] = res[0]; sh[1][t] = res[1];
    // zero accumulators for next iter
    g_U[(row0+0)*256 + t] = 0.f;
    g_U[(row0+1)*256 + t] = 0.f;
    if (t < 2) { g_cs[row0 + t] = 0.f; g_t1[row0 + t] = 0.f; }
    __syncthreads();
    if (w < 2) {
        float s1 = 0.f, s2 = 0.f;
        #pragma unroll
        for (int e = 0; e < 8; e++) {
            float v = sh[w][lane + e*32];
            s1 += v; s2 += v*v;
        }
        #pragma unroll
        for (int oo = 16; oo; oo >>= 1) {
            s1 += __shfl_xor_sync(0xffffffffu, s1, oo);
            s2 += __shfl_xor_sync(0xffffffffu, s2, oo);
        }
        if (lane == 0) {
            float m = s1 * (1.f/256.f);
            sm[w] = m;
            sr2[w] = rsqrtf(s2 * (1.f/256.f) - m*m + EPS);
        }
    }
    __syncthreads();
    float gst = lsg[t], bst = lsb[t];
    sa[0][t] = (res[0] - sm[0]) * sr2[0] * gst + bst;
    sa[1][t] = (res[1] - sm[1]) * sr2[1] * gst + bst;
    __syncthreads();

    // q[sl][t] = sa[sl]·wq[t,:] + bq[t]
    {
        float q0 = 0.f, q1 = 0.f;
        const float* wr = wq + (size_t)t * 256;
        #pragma unroll 2
        for (int e = 0; e < 256; e += 4) {
            float4 w4 = *(const float4*)&wr[e];
            float4 s0 = *(const float4*)&sa[0][e];
            float4 s1v = *(const float4*)&sa[1][e];
            q0 += w4.x*s0.x + w4.y*s0.y + w4.z*s0.z + w4.w*s0.w;
            q1 += w4.x*s1v.x + w4.y*s1v.y + w4.z*s1v.z + w4.w*s1v.w;
        }
        float bqt = bq[t];
        szn[0][t] = q0 + bqt;
        szn[1][t] = q1 + bqt;
    }
    __syncthreads();

    // pg[sl][t] = SCALE * q[sl]·wkgT[t,:]; S1, S2
    float pg0 = 0.f, pg1 = 0.f;
    {
        const float* wr = g_wkgT + (size_t)t * 256;
        #pragma unroll 2
        for (int e = 0; e < 256; e += 4) {
            float4 w4 = *(const float4*)&wr[e];
            float4 q0 = *(const float4*)&szn[0][e];
            float4 q1 = *(const float4*)&szn[1][e];
            pg0 += w4.x*q0.x + w4.y*q0.y + w4.z*q0.z + w4.w*q0.w;
            pg1 += w4.x*q1.x + w4.y*q1.y + w4.z*q1.z + w4.w*q1.w;
        }
    }
    pg0 *= SCALE; pg1 *= SCALE;
    g_p[(row0+0)*256 + t] = pg0;
    g_p[(row0+1)*256 + t] = pg1;
    float wkbt = g_wkb[t];
    float p20 = szn[0][t] * wkbt;
    float p21 = szn[1][t] * wkbt;
    {
        float v0 = pg0, v1 = pg1, v2 = p20, v3 = p21;
        #pragma unroll
        for (int oo = 16; oo; oo >>= 1) {
            v0 += __shfl_xor_sync(0xffffffffu, v0, oo);
            v1 += __shfl_xor_sync(0xffffffffu, v1, oo);
            v2 += __shfl_xor_sync(0xffffffffu, v2, oo);
            v3 += __shfl_xor_sync(0xffffffffu, v3, oo);
        }
        if (lane == 0) {
            red1[0][w] = v0; red1[1][w] = v1;
            red2[0][w] = v2; red2[1][w] = v3;
        }
    }
    __syncthreads();
    if (t < 2) {
        float a1s = 0.f, a2s = 0.f;
        #pragma unroll
        for (int i = 0; i < 8; i++) { a1s += red1[t][i]; a2s += red2[t][i]; }
        g_S1[row0 + t] = a1s;
        g_S2[row0 + t] = a2s * SCALE;
    }
}

// ---------------- K8: final attn normalize to d_out --------------------------
__global__ void k_attn_out(float* __restrict__ dst) {
    int i = blockIdx.x*blockDim.x + threadIdx.x;
    if (i < TOK*S_) {
        int s = i & 7;
        int b = i >> 15;
        dst[i] = g_attn[i] / g_cs[b*8 + s];
    }
}

// ---------------- host --------------------------------------------------------
extern "C" void kernel_launch(void* const* d_in, const int* in_sizes, int n_in,
                              void* d_out, int out_size) {
    const float* inputs     = (const float*)d_in[0];
    const float* init_noise = (const float*)d_in[1];
    const float* mu         = (const float*)d_in[2];
    const float* sigma_raw  = (const float*)d_in[3];
    const float* ln_in_g    = (const float*)d_in[4];
    const float* ln_in_b    = (const float*)d_in[5];
    const float* ln_s_g     = (const float*)d_in[6];
    const float* ln_s_b     = (const float*)d_in[7];
    const float* ln_m_g     = (const float*)d_in[8];
    const float* ln_m_b     = (const float*)d_in[9];
    const float* wq         = (const float*)d_in[10];
    const float* bq         = (const float*)d_in[11];
    const float* wk         = (const float*)d_in[12];
    const float* bk         = (const float*)d_in[13];
    const float* wv         = (const float*)d_in[14];
    const float* bv         = (const float*)d_in[15];
    const float* w_ih       = (const float*)d_in[16];
    const float* w_hh       = (const float*)d_in[17];
    const float* b_ih       = (const float*)d_in[18];
    const float* b_hh       = (const float*)d_in[19];
    const float* w1         = (const float*)d_in[20];
    const float* b1         = (const float*)d_in[21];
    const float* w2         = (const float*)d_in[22];
    const float* b2         = (const float*)d_in[23];
    float* out = (float*)d_out;

    k_prep_all<<<65, 256>>>(wk, ln_in_g, ln_in_b, bk);
    k_meanvar<<<TOK/8, 256>>>(inputs);
    k_qproj3<<<B_, 256>>>(ln_s_g, ln_s_b, wq, bq, init_noise, mu, sigma_raw);

    for (int it = 0; it < 3; ++it) {
        bool last = (it == 2);
        k_attn5<<<dim3(32, B_), 256>>>(inputs, last ? 1 : 0);
        k_gruq<<<B_*4, 256>>>(ln_in_g, ln_in_b, wv, bv,
                              w_ih, w_hh, b_ih, b_hh, ln_m_g, ln_m_b,
                              w1, b1, w2, b2,
                              ln_s_g, ln_s_b, wq, bq,
                              last ? 0 : 1, last ? out : nullptr);
        if (last) k_attn_out<<<(TOK*S_ + 255)/256, 256>>>(out + B_*S_*D_);
    }
}